// round 2
// baseline (speedup 1.0000x reference)
#include <cuda_runtime.h>
#include <math.h>

// ---------------- problem constants ----------------
#define Bz   8
#define Cch  256
#define Hh   64
#define Ww   64
#define HQ   32
#define WQ   32
#define Lq   1024          // HQ*WQ
#define NHh  8
#define HD   8             // ED_QK/NH
#define DV   32            // ED_V/NH
#define BL   8192          // Bz*Lq
#define L2   4096          // Hh*Ww
#define BL2  32768         // Bz*L2

// ---------------- scratch (__device__ globals; allocation-free launch) ----
__device__ float g_X1[1024 * 8192];                 // im2col pos proj (k=c*4+ky*2+kx)
__device__ float g_W1[384 * 1024];                  // packed q/k/v weights
__device__ float g_b1[384];
__device__ float g_P1[384 * 8192];                  // proj out [oc][b*L+l]
__device__ float g_Pattn[(size_t)64 * 1024 * 1024]; // probs [bh][q][k]
__device__ float g_Vr[64 * 1024 * 32];              // V [bh][k][d]
__device__ float g_O1[64 * 1024 * 32];              // attn out [bh][l][d]
__device__ float g_OP[256 * 8192];                  // op [c][b*L+l]
__device__ float g_X2[2304 * 8192];                 // im2col 3x3 pos
__device__ float g_O2[256 * 8192];                  // conv3x3 out
__device__ float g_outpos[8 * 256 * 4096];
__device__ float g_qc[8 * 2048 * 1024];             // [b][flat_ch][l]
__device__ float g_kc[8 * 2048 * 1024];
__device__ float g_vc[8 * 2048 * 1024];
__device__ float g_Sc[64 * 256 * 256];              // cha scores/probs
__device__ float g_oc[8 * 2048 * 1024];
__device__ float g_outcha[8 * 256 * 4096];
__device__ float g_X3[(size_t)4608 * 32768];        // im2col fusion
__device__ float g_O3[256 * 32768];                 // fusion out [oc][b*L2+pix]

// ---------------- generic SGEMM: C[M,N] = A[M,K] * B(K,N or N,K) + bias[m] --
// Requirements (all call sites satisfy): M%128==0, K%16==0, N%BN==0.
template <int BN, bool TRANSB>
__global__ __launch_bounds__(256) void sgemm_kernel(
    const float* __restrict__ A, const float* __restrict__ B,
    float* __restrict__ C, const float* __restrict__ bias,
    int M, int N, int K, long sA, long sB, long sC)
{
    constexpr int BM = 128, BK = 16;
    constexpr int TM = 8, TN = BN / 16;
    __shared__ float As[BK][BM + 4];
    __shared__ float Bs[BK][BN];

    const float* Ab = A + (long)blockIdx.z * sA;
    const float* Bb = B + (long)blockIdx.z * sB;
    float* Cb = C + (long)blockIdx.z * sC;

    const int m0 = blockIdx.y * BM;
    const int n0 = blockIdx.x * BN;
    const int tid = threadIdx.x;
    const int tx = tid & 15, ty = tid >> 4;

    float acc[TM][TN];
#pragma unroll
    for (int i = 0; i < TM; i++)
#pragma unroll
        for (int j = 0; j < TN; j++) acc[i][j] = 0.0f;

    float4 rA[2];
    float4 rB;

    auto loadA = [&](int k0) {
#pragma unroll
        for (int i = 0; i < 2; i++) {
            int f = tid + i * 256;
            int m = f >> 2, kc = (f & 3) << 2;
            rA[i] = *(const float4*)(Ab + (long)(m0 + m) * K + (k0 + kc));
        }
    };
    auto storeA = [&]() {
#pragma unroll
        for (int i = 0; i < 2; i++) {
            int f = tid + i * 256;
            int m = f >> 2, kc = (f & 3) << 2;
            As[kc + 0][m] = rA[i].x; As[kc + 1][m] = rA[i].y;
            As[kc + 2][m] = rA[i].z; As[kc + 3][m] = rA[i].w;
        }
    };
    auto loadB = [&](int k0) {
        if (!TRANSB) {
            constexpr int TOT = BK * BN / 4;       // float4 count
            if (TOT >= 256 || tid < TOT) {
                constexpr int R = BN / 4;          // float4 per k-row
                int kr = tid / R, nc = (tid % R) << 2;
                rB = *(const float4*)(Bb + (long)(k0 + kr) * N + (n0 + nc));
            }
        } else {
            constexpr int TOT = BN * 4;            // BN rows x 4 float4
            if (TOT >= 256 || tid < TOT) {
                int n = tid >> 2, kc = (tid & 3) << 2;
                rB = *(const float4*)(Bb + (long)(n0 + n) * K + (k0 + kc));
            }
        }
    };
    auto storeB = [&]() {
        if (!TRANSB) {
            constexpr int TOT = BK * BN / 4;
            if (TOT >= 256 || tid < TOT) {
                constexpr int R = BN / 4;
                int kr = tid / R, nc = (tid % R) << 2;
                *(float4*)&Bs[kr][nc] = rB;
            }
        } else {
            constexpr int TOT = BN * 4;
            if (TOT >= 256 || tid < TOT) {
                int n = tid >> 2, kc = (tid & 3) << 2;
                Bs[kc + 0][n] = rB.x; Bs[kc + 1][n] = rB.y;
                Bs[kc + 2][n] = rB.z; Bs[kc + 3][n] = rB.w;
            }
        }
    };

    loadA(0); loadB(0);
    storeA(); storeB();
    __syncthreads();

    for (int k0 = BK; k0 < K + BK; k0 += BK) {
        bool more = (k0 < K);
        if (more) { loadA(k0); loadB(k0); }
#pragma unroll
        for (int kk = 0; kk < BK; kk++) {
            float a[TM], bv[TN];
#pragma unroll
            for (int i = 0; i < TM; i++) a[i] = As[kk][ty * TM + i];
#pragma unroll
            for (int j = 0; j < TN; j++) bv[j] = Bs[kk][tx * TN + j];
#pragma unroll
            for (int i = 0; i < TM; i++)
#pragma unroll
                for (int j = 0; j < TN; j++) acc[i][j] += a[i] * bv[j];
        }
        __syncthreads();
        if (more) { storeA(); storeB(); __syncthreads(); }
    }

#pragma unroll
    for (int i = 0; i < TM; i++) {
        int m = m0 + ty * TM + i;
        float bb = bias ? bias[m] : 0.0f;
#pragma unroll
        for (int j = 0; j < TN; j++)
            Cb[(long)m * N + (n0 + tx * TN + j)] = acc[i][j] + bb;
    }
}

// ---------------- small helpers ----------------
__device__ __forceinline__ float warp_max(float v) {
#pragma unroll
    for (int o = 16; o; o >>= 1) v = fmaxf(v, __shfl_xor_sync(0xffffffffu, v, o));
    return v;
}
__device__ __forceinline__ float warp_sum(float v) {
#pragma unroll
    for (int o = 16; o; o >>= 1) v += __shfl_xor_sync(0xffffffffu, v, o);
    return v;
}

// ---------------- kernels ----------------
__global__ void k_pack_w1(const float* __restrict__ Wq, const float* __restrict__ bq,
                          const float* __restrict__ Wk, const float* __restrict__ bk,
                          const float* __restrict__ Wv, const float* __restrict__ bv) {
    int idx = blockIdx.x * 256 + threadIdx.x;   // 0..393215
    if (idx < 64 * 1024)        g_W1[idx] = Wq[idx];
    else if (idx < 128 * 1024)  g_W1[idx] = Wk[idx - 65536];
    else                        g_W1[idx] = Wv[idx - 131072];
    if (idx < 64)               g_b1[idx] = bq[idx];
    else if (idx < 128)         g_b1[idx] = bk[idx - 64];
    else if (idx < 384)         g_b1[idx] = bv[idx - 128];
}

__global__ void k_im2col_x1(const float* __restrict__ x) {
    int idx = blockIdx.x * 256 + threadIdx.x;   // 1024*8192
    int n = idx & 8191, k = idx >> 13;
    int c = k >> 2, ky = (k >> 1) & 1, kx = k & 1;
    int b = n >> 10, l = n & 1023, y = l >> 5, xq = l & 31;
    g_X1[idx] = x[(((b * 256 + c) * 64) + (y * 2 + ky)) * 64 + xq * 2 + kx];
}

// fused pos attention: scores + softmax -> g_Pattn. grid(128, NH, B), block 256
__global__ void k_pos_attn() {
    __shared__ float Ks[8][1024];
    int b = blockIdx.z, h = blockIdx.y;
    int tid = threadIdx.x;
    for (int idx = tid; idx < 8 * 1024; idx += 256) {
        int d = idx >> 10, k = idx & 1023;
        Ks[d][k] = g_P1[(64 + h * 8 + d) * BL + b * 1024 + k];
    }
    __syncthreads();
    int warp = tid >> 5, lane = tid & 31;
    int q = blockIdx.x * 8 + warp;
    float Q[8];
#pragma unroll
    for (int d = 0; d < 8; d++) Q[d] = g_P1[(h * 8 + d) * BL + b * 1024 + q];

    float s[32];
    float mx = -1e30f;
#pragma unroll
    for (int i = 0; i < 32; i++) {
        int k = i * 32 + lane;
        float sc = 0.f;
#pragma unroll
        for (int d = 0; d < 8; d++) sc += Q[d] * Ks[d][k];
        sc *= 0.35355339059327373f;   // hd^-0.5
        s[i] = sc;
        mx = fmaxf(mx, sc);
    }
    mx = warp_max(mx);
    float sum = 0.f;
#pragma unroll
    for (int i = 0; i < 32; i++) { float e = __expf(s[i] - mx); s[i] = e; sum += e; }
    sum = warp_sum(sum);
    float inv = 1.0f / sum;
    float* out = g_Pattn + ((size_t)(b * 8 + h) * 1024 + q) * 1024;
#pragma unroll
    for (int i = 0; i < 32; i++) out[i * 32 + lane] = s[i] * inv;
}

__global__ void k_vr_repack() {
    int idx = blockIdx.x * 256 + threadIdx.x;   // 64*1024*32
    int d = idx & 31, k = (idx >> 5) & 1023, bh = idx >> 15;
    int b = bh >> 3, h = bh & 7;
    g_Vr[idx] = g_P1[(128 + h * 32 + d) * BL + b * 1024 + k];
}

__global__ void k_op_repack() {
    int idx = blockIdx.x * 256 + threadIdx.x;   // 256*8192
    int n = idx & 8191, c = idx >> 13;
    int b = n >> 10, l = n & 1023;
    g_OP[idx] = g_O1[((b * 8 + (c >> 5)) * 1024 + l) * 32 + (c & 31)];
}

__global__ void k_im2col_x2() {
    int idx = blockIdx.x * 256 + threadIdx.x;   // 2304*8192
    int n = idx & 8191, k2 = idx >> 13;
    int c = k2 / 9, tap = k2 - c * 9;
    int dy = tap / 3 - 1, dx = tap - (tap / 3) * 3 - 1;
    int b = n >> 10, l = n & 1023, y = l >> 5, xq = l & 31;
    int yy = y + dy, xx = xq + dx;
    float v = 0.f;
    if ((unsigned)yy < 32u && (unsigned)xx < 32u)
        v = g_OP[c * 8192 + b * 1024 + yy * 32 + xx];
    g_X2[idx] = v;
}

__global__ void k_upsample_residual(const float* __restrict__ x, const float* __restrict__ gamma) {
    int idx = blockIdx.x * 256 + threadIdx.x;   // 8*256*4096
    int pix = idx & 4095, c = (idx >> 12) & 255, b = idx >> 20;
    int Y = pix >> 6, X = pix & 63;
    float sy = Y * 0.5f - 0.25f, sx = X * 0.5f - 0.25f;
    int y0 = (int)floorf(sy); float fy = sy - (float)y0;
    int x0 = (int)floorf(sx); float fx = sx - (float)x0;
    int y1 = min(y0 + 1, 31); y0 = max(y0, 0);
    int x1 = min(x0 + 1, 31); x0 = max(x0, 0);
    const float* p = g_O2 + c * 8192 + b * 1024;
    float v00 = p[y0 * 32 + x0], v01 = p[y0 * 32 + x1];
    float v10 = p[y1 * 32 + x0], v11 = p[y1 * 32 + x1];
    float v = (1.f - fy) * ((1.f - fx) * v00 + fx * v01) + fy * ((1.f - fx) * v10 + fx * v11);
    g_outpos[idx] = x[idx] + gamma[0] * v;
}

__global__ void k_cha_proj(const float* __restrict__ x,
                           const float* __restrict__ Wq, const float* __restrict__ bq,
                           const float* __restrict__ Wk, const float* __restrict__ bk,
                           const float* __restrict__ Wv, const float* __restrict__ bv) {
    int l = blockIdx.x * 256 + threadIdx.x;
    int g = blockIdx.y, b = blockIdx.z;
    int i = l >> 5, j = l & 31;
    const float* xp = x + ((b * 256 + g) * 64) * 64;
    float x00 = xp[(2 * i) * 64 + 2 * j],     x01 = xp[(2 * i) * 64 + 2 * j + 1];
    float x10 = xp[(2 * i + 1) * 64 + 2 * j], x11 = xp[(2 * i + 1) * 64 + 2 * j + 1];
    int base = (b * 2048 + g * 8) * 1024 + l;
#pragma unroll
    for (int h = 0; h < 8; h++) {
        int w = (g * 8 + h) * 4;
        g_qc[base + h * 1024] = Wq[w] * x00 + Wq[w + 1] * x01 + Wq[w + 2] * x10 + Wq[w + 3] * x11 + bq[g * 8 + h];
        g_kc[base + h * 1024] = Wk[w] * x00 + Wk[w + 1] * x01 + Wk[w + 2] * x10 + Wk[w + 3] * x11 + bk[g * 8 + h];
        g_vc[base + h * 1024] = Wv[w] * x00 + Wv[w + 1] * x01 + Wv[w + 2] * x10 + Wv[w + 3] * x11 + bv[g * 8 + h];
    }
}

__global__ void k_cha_softmax() {
    int row = blockIdx.x * 8 + (threadIdx.x >> 5);  // 16384 rows
    int lane = threadIdx.x & 31;
    float* r = g_Sc + row * 256;
    float v[8];
    float mx = -1e30f;
#pragma unroll
    for (int j = 0; j < 8; j++) { v[j] = r[j * 32 + lane] * 0.03125f; mx = fmaxf(mx, v[j]); }
    mx = warp_max(mx);
    float sum = 0.f;
#pragma unroll
    for (int j = 0; j < 8; j++) { v[j] = __expf(v[j] - mx); sum += v[j]; }
    sum = warp_sum(sum);
    float inv = 1.0f / sum;
#pragma unroll
    for (int j = 0; j < 8; j++) r[j * 32 + lane] = v[j] * inv;
}

__global__ void k_ct_residual(const float* __restrict__ x, const float* __restrict__ Wt,
                              const float* __restrict__ bt, const float* __restrict__ gamma) {
    int pix = blockIdx.x * 256 + threadIdx.x;
    int g = blockIdx.y, b = blockIdx.z;
    int Y = pix >> 6, X = pix & 63;
    int p = Y >> 1, ky = Y & 1, q = X >> 1, kx = X & 1;
    float s = bt[g];
    int obase = (b * 2048 + g * 8) * 1024 + p * 32 + q;
#pragma unroll
    for (int i = 0; i < 8; i++)
        s += g_oc[obase + i * 1024] * Wt[(g * 8 + i) * 4 + ky * 2 + kx];
    int idx = ((b * 256 + g) * 4096) + pix;
    g_outcha[idx] = x[idx] + gamma[0] * s;
}

__global__ void k_im2col_x3() {
    int idx = blockIdx.x * 256 + threadIdx.x;   // 4608*32768
    int n = idx & 32767, k3 = idx >> 15;
    int cc = k3 / 9, tap = k3 - cc * 9;
    int dy = tap / 3 - 1, dx = tap - (tap / 3) * 3 - 1;
    int b = n >> 12, pix = n & 4095, Y = pix >> 6, X = pix & 63;
    int YY = Y + dy, XX = X + dx;
    float v = 0.f;
    if ((unsigned)YY < 64u && (unsigned)XX < 64u) {
        const float* src = (cc < 256) ? (g_outpos + ((b * 256 + cc) * 4096))
                                      : (g_outcha + ((b * 256 + cc - 256) * 4096));
        v = src[YY * 64 + XX];
    }
    g_X3[(size_t)idx] = v;
}

__global__ void k_out_permute(float* __restrict__ out) {
    int idx = blockIdx.x * 256 + threadIdx.x;   // 8*256*4096
    int pix = idx & 4095, ocb = idx >> 12;
    int oc = ocb & 255, b = ocb >> 8;
    out[idx] = g_O3[oc * 32768 + b * 4096 + pix];
}

// ---------------- launch ----------------
static float* symaddr(const void* sym) {
    void* p = nullptr;
    cudaGetSymbolAddress(&p, sym);
    return (float*)p;
}

extern "C" void kernel_launch(void* const* d_in, const int* in_sizes, int n_in,
                              void* d_out, int out_size) {
    const float* qkv_pos  = (const float*)d_in[0];
    const float* qkv_cha  = (const float*)d_in[1];
    const float* Wq_pos   = (const float*)d_in[2];
    const float* bq_pos   = (const float*)d_in[3];
    const float* Wk_pos   = (const float*)d_in[4];
    const float* bk_pos   = (const float*)d_in[5];
    const float* Wv_pos   = (const float*)d_in[6];
    const float* bv_pos   = (const float*)d_in[7];
    const float* Wo_pos   = (const float*)d_in[8];
    const float* bo_pos   = (const float*)d_in[9];
    const float* gamma_pos= (const float*)d_in[10];
    const float* Wq_cha   = (const float*)d_in[11];
    const float* bq_cha   = (const float*)d_in[12];
    const float* Wk_cha   = (const float*)d_in[13];
    const float* bk_cha   = (const float*)d_in[14];
    const float* Wv_cha   = (const float*)d_in[15];
    const float* bv_cha   = (const float*)d_in[16];
    const float* Wt_cha   = (const float*)d_in[17];
    const float* bt_cha   = (const float*)d_in[18];
    const float* gamma_cha= (const float*)d_in[19];
    const float* Wf       = (const float*)d_in[20];
    const float* bf       = (const float*)d_in[21];
    float* out = (float*)d_out;

    float* pX1    = symaddr(g_X1);
    float* pW1    = symaddr(g_W1);
    float* pb1    = symaddr(g_b1);
    float* pP1    = symaddr(g_P1);
    float* pPattn = symaddr(g_Pattn);
    float* pVr    = symaddr(g_Vr);
    float* pO1    = symaddr(g_O1);
    float* pX2    = symaddr(g_X2);
    float* pO2    = symaddr(g_O2);
    float* pqc    = symaddr(g_qc);
    float* pkc    = symaddr(g_kc);
    float* pvc    = symaddr(g_vc);
    float* pSc    = symaddr(g_Sc);
    float* poc    = symaddr(g_oc);
    float* pX3    = symaddr(g_X3);
    float* pO3    = symaddr(g_O3);

    // ---- POS branch ----
    k_pack_w1<<<(384 * 1024) / 256, 256>>>(Wq_pos, bq_pos, Wk_pos, bk_pos, Wv_pos, bv_pos);
    k_im2col_x1<<<(1024 * 8192) / 256, 256>>>(qkv_pos);
    // qkv proj GEMM: (384 x 1024) @ (1024 x 8192)
    sgemm_kernel<64, false><<<dim3(8192 / 64, 384 / 128, 1), 256>>>(
        pW1, pX1, pP1, pb1, 384, 8192, 1024, 0, 0, 0);
    // fused scores + softmax
    k_pos_attn<<<dim3(128, NHh, Bz), 256>>>();
    k_vr_repack<<<(64 * 1024 * 32) / 256, 256>>>();
    // P @ V (batched 64): (1024 x 1024) @ (1024 x 32)
    sgemm_kernel<32, false><<<dim3(1, 1024 / 128, 64), 256>>>(
        pPattn, pVr, pO1, nullptr, 1024, 32, 1024,
        (long)1024 * 1024, (long)1024 * 32, (long)1024 * 32);
    k_op_repack<<<(256 * 8192) / 256, 256>>>();
    k_im2col_x2<<<(2304 * 8192) / 256, 256>>>();
    // conv3x3 pos GEMM: (256 x 2304) @ (2304 x 8192)
    sgemm_kernel<64, false><<<dim3(8192 / 64, 256 / 128, 1), 256>>>(
        Wo_pos, pX2, pO2, bo_pos, 256, 8192, 2304, 0, 0, 0);
    k_upsample_residual<<<(8 * 256 * 4096) / 256, 256>>>(qkv_pos, gamma_pos);

    // ---- CHA branch ----
    k_cha_proj<<<dim3(1024 / 256, 256, Bz), 256>>>(qkv_cha, Wq_cha, bq_cha, Wk_cha, bk_cha, Wv_cha, bv_cha);
    // S = qc @ kc^T (batched 64): (256 x 1024) @ (1024 x 256)
    sgemm_kernel<64, true><<<dim3(256 / 64, 256 / 128, 64), 256>>>(
        pqc, pkc, pSc, nullptr, 256, 256, 1024,
        (long)256 * 1024, (long)256 * 1024, (long)256 * 256);
    k_cha_softmax<<<(64 * 256) / 8, 256>>>();
    // oc = P @ vc (batched 64): (256 x 256) @ (256 x 1024)
    sgemm_kernel<64, false><<<dim3(1024 / 64, 256 / 128, 64), 256>>>(
        pSc, pvc, poc, nullptr, 256, 1024, 256,
        (long)256 * 256, (long)256 * 1024, (long)256 * 1024);
    k_ct_residual<<<dim3(4096 / 256, 256, Bz), 256>>>(qkv_cha, Wt_cha, bt_cha, gamma_cha);

    // ---- fusion conv 512->256 3x3 ----
    k_im2col_x3<<<(int)(((size_t)4608 * 32768) / 256), 256>>>();
    sgemm_kernel<64, false><<<dim3(32768 / 64, 256 / 128, 1), 256>>>(
        Wf, pX3, pO3, bf, 256, 32768, 4608, 0, 0, 0);
    k_out_permute<<<(8 * 256 * 4096) / 256, 256>>>(out);
}

// round 4
// speedup vs baseline: 1.7386x; 1.7386x over previous
#include <cuda_runtime.h>
#include <cuda_bf16.h>
#include <math.h>
#include <stdint.h>

#define Bz 8
#define BL 8192

__device__ __forceinline__ uint32_t smem_u32(const void* p) {
    uint32_t a;
    asm("{ .reg .u64 t; cvta.to.shared.u64 t, %1; cvt.u32.u64 %0, t; }" : "=r"(a) : "l"(p));
    return a;
}
__device__ __forceinline__ void cp16(uint32_t s, const void* g) {
    unsigned long long ga = (unsigned long long)__cvta_generic_to_global(g);
    asm volatile("cp.async.cg.shared.global [%0], [%1], 16;" :: "r"(s), "l"(ga));
}
__device__ __forceinline__ void ldsm4(uint32_t* r, uint32_t a) {
    asm volatile("ldmatrix.sync.aligned.m8n8.x4.shared.b16 {%0,%1,%2,%3}, [%4];"
                 : "=r"(r[0]), "=r"(r[1]), "=r"(r[2]), "=r"(r[3]) : "r"(a));
}
__device__ __forceinline__ void mma16816(float* c, const uint32_t* a, const uint32_t* b) {
    asm volatile("mma.sync.aligned.m16n8k16.row.col.f32.bf16.bf16.f32 "
                 "{%0,%1,%2,%3}, {%4,%5,%6,%7}, {%8,%9}, {%0,%1,%2,%3};"
                 : "+f"(c[0]), "+f"(c[1]), "+f"(c[2]), "+f"(c[3])
                 : "r"(a[0]), "r"(a[1]), "r"(a[2]), "r"(a[3]), "r"(b[0]), "r"(b[1]));
}
__device__ __forceinline__ void bsplit(float v, __nv_bfloat16& h, __nv_bfloat16& l) {
    h = __float2bfloat16(v);
    l = __float2bfloat16(v - __bfloat162float(h));
}

// ---------------- scratch ----------------
#define AL __align__(256)
__device__ AL __nv_bfloat16 g_W1h[384*1024], g_W1l[384*1024];
__device__ float g_b1[384];
__device__ AL __nv_bfloat16 g_X1h[8192*1024], g_X1l[8192*1024];
__device__ float g_P1[384*8192];
__device__ float g_Pattn[(size_t)64*1024*1024];
__device__ float g_Vr[64*1024*32];
__device__ float g_O1[64*1024*32];
__device__ float g_OP[256*8192];
__device__ AL __nv_bfloat16 g_Woh[256*2304], g_Wol[256*2304];
__device__ AL __nv_bfloat16 g_X2h[8192*2304], g_X2l[8192*2304];
__device__ float g_O2[256*8192];
__device__ float g_outpos[8*256*4096];
__device__ AL __nv_bfloat16 g_qch[8*2048*1024], g_qcl[8*2048*1024];
__device__ AL __nv_bfloat16 g_kch[8*2048*1024], g_kcl[8*2048*1024];
__device__ float g_vc[8*2048*1024];
__device__ AL __nv_bfloat16 g_vTh[64*1024*256], g_vTl[64*1024*256];
__device__ float g_Sc[64*256*256];
__device__ AL __nv_bfloat16 g_Pch[64*256*256], g_Pcl[64*256*256];
__device__ float g_oc[8*2048*1024];
__device__ float g_outcha[8*256*4096];
__device__ AL __nv_bfloat16 g_Wfh[256*4608], g_Wfl[256*4608];
__device__ AL __nv_bfloat16 g_X3h[(size_t)32768*4608], g_X3l[(size_t)32768*4608];
__device__ float g_O3[256*32768];

// ========= mma.sync split-bf16 GEMM =========
// C[z][m][n] = sum_k A[z][m][k]*B[z][n][k] (+bias[m]); exact-ish via 3-term split.
// CTA tile M=128 (grid.y), N=128 (grid.x), BK=32, K%32==0. 8 warps (2x4).
// smem per stage: 4 tensors (Ah,Al,Bh,Bl) x 128 rows x 40 bf16 pitch (80B) = 40960B.
#define PITCHB 80
#define TSZ 10240
#define STGSZ 40960
#define TSMEM (2*STGSZ)

__global__ __launch_bounds__(256) void tgemm(
    const __nv_bfloat16* __restrict__ Ah, const __nv_bfloat16* __restrict__ Al,
    const __nv_bfloat16* __restrict__ Bh, const __nv_bfloat16* __restrict__ Bl,
    float* __restrict__ C, const float* __restrict__ bias,
    int N, int K, long sA, long sB, long sC)
{
    extern __shared__ __align__(128) char smem_raw[];
    const uint32_t sb = smem_u32(smem_raw);
    const int tid = threadIdx.x, wid = tid >> 5, lane = tid & 31;
    const int wm = wid >> 2, wn = wid & 3;
    const int m0 = blockIdx.y * 128, n0 = blockIdx.x * 128;

    const __nv_bfloat16* gp[4] = {
        Ah + (long)blockIdx.z * sA + (long)m0 * K,
        Al + (long)blockIdx.z * sA + (long)m0 * K,
        Bh + (long)blockIdx.z * sB + (long)n0 * K,
        Bl + (long)blockIdx.z * sB + (long)n0 * K };

    // ldmatrix lane addressing
    const int lg = lane >> 3, l8 = lane & 7;
    const int row_off = l8 + (lg & 1) * 8;     // 0..15
    const int kadd = (lg >> 1) * 8;            // bf16
    const int rowA = wm * 64 + row_off;
    const int rowB = wn * 32 + row_off;

    float acc[4][4][4];
#pragma unroll
    for (int a = 0; a < 4; a++)
#pragma unroll
        for (int b = 0; b < 4; b++)
#pragma unroll
            for (int c = 0; c < 4; c++) acc[a][b][c] = 0.f;

    const int nch = K >> 5;
    auto load_stage = [&](int ch, int st) {
        uint32_t base = sb + st * STGSZ;
        int k0 = ch << 5;
#pragma unroll
        for (int j = 0; j < 8; j++) {
            int id = tid + j * 256;          // 0..2047
            int t = id >> 9, w = id & 511;   // tensor, chunk
            int row = w >> 2, c16 = (w & 3);
            cp16(base + t * TSZ + row * PITCHB + c16 * 16,
                 gp[t] + (long)row * K + k0 + c16 * 8);
        }
        asm volatile("cp.async.commit_group;" ::: "memory");
    };

    load_stage(0, 0);
    for (int i = 0; i < nch; i++) {
        int st = i & 1;
        if (i + 1 < nch) {
            load_stage(i + 1, st ^ 1);
            asm volatile("cp.async.wait_group 1;" ::: "memory");
        } else {
            asm volatile("cp.async.wait_group 0;" ::: "memory");
        }
        __syncthreads();
        uint32_t sA_h = sb + st * STGSZ, sA_l = sA_h + TSZ;
        uint32_t sB_h = sA_h + 2 * TSZ, sB_l = sA_h + 3 * TSZ;
#pragma unroll
        for (int ks = 0; ks < 2; ks++) {
            uint32_t kb = (uint32_t)(ks * 16 + kadd) * 2;
            uint32_t bh[4][2], bl[4][2];
#pragma unroll
            for (int p = 0; p < 2; p++) {
                uint32_t r[4];
                ldsm4(r, sB_h + (uint32_t)(rowB + p * 16) * PITCHB + kb);
                bh[p*2][0] = r[0]; bh[p*2][1] = r[2];
                bh[p*2+1][0] = r[1]; bh[p*2+1][1] = r[3];
                ldsm4(r, sB_l + (uint32_t)(rowB + p * 16) * PITCHB + kb);
                bl[p*2][0] = r[0]; bl[p*2][1] = r[2];
                bl[p*2+1][0] = r[1]; bl[p*2+1][1] = r[3];
            }
#pragma unroll
            for (int mt = 0; mt < 4; mt++) {
                uint32_t ah[4], al[4];
                ldsm4(ah, sA_h + (uint32_t)(rowA + mt * 16) * PITCHB + kb);
                ldsm4(al, sA_l + (uint32_t)(rowA + mt * 16) * PITCHB + kb);
#pragma unroll
                for (int nt = 0; nt < 4; nt++) {
                    mma16816(acc[mt][nt], ah, bh[nt]);
                    mma16816(acc[mt][nt], ah, bl[nt]);
                    mma16816(acc[mt][nt], al, bh[nt]);
                }
            }
        }
        __syncthreads();
    }

    float* Cb = C + (long)blockIdx.z * sC;
#pragma unroll
    for (int mt = 0; mt < 4; mt++) {
        int m = m0 + wm * 64 + mt * 16 + (lane >> 2);
        float b0 = bias ? bias[m] : 0.f;
        float b1 = bias ? bias[m + 8] : 0.f;
#pragma unroll
        for (int nt = 0; nt < 4; nt++) {
            int n = n0 + wn * 32 + nt * 8 + (lane & 3) * 2;
            float2 v0 = { acc[mt][nt][0] + b0, acc[mt][nt][1] + b0 };
            float2 v1 = { acc[mt][nt][2] + b1, acc[mt][nt][3] + b1 };
            *(float2*)(Cb + (long)m * N + n) = v0;
            *(float2*)(Cb + (long)(m + 8) * N + n) = v1;
        }
    }
}

// ================= fp32 SGEMM (pos P@V, N=32) =================
__global__ __launch_bounds__(256) void sgemm32(
    const float* __restrict__ A, const float* __restrict__ B, float* __restrict__ C,
    int N, int K, long sA, long sB, long sC)
{
    constexpr int BM = 128, BK = 16, BN = 32, TM = 8, TN = 2;
    __shared__ float As[BK][BM + 4];
    __shared__ float Bs[BK][BN];
    const float* Ab = A + (long)blockIdx.z * sA;
    const float* Bb = B + (long)blockIdx.z * sB;
    float* Cb = C + (long)blockIdx.z * sC;
    const int m0 = blockIdx.y * BM, n0 = blockIdx.x * BN;
    const int tid = threadIdx.x, tx = tid & 15, ty = tid >> 4;
    float acc[TM][TN] = {};
    float4 rA[2]; float4 rB;
    auto loadA = [&](int k0) {
#pragma unroll
        for (int i = 0; i < 2; i++) {
            int f = tid + i * 256, m = f >> 2, kc = (f & 3) << 2;
            rA[i] = *(const float4*)(Ab + (long)(m0 + m) * K + (k0 + kc));
        }
    };
    auto stoA = [&]() {
#pragma unroll
        for (int i = 0; i < 2; i++) {
            int f = tid + i * 256, m = f >> 2, kc = (f & 3) << 2;
            As[kc][m] = rA[i].x; As[kc+1][m] = rA[i].y; As[kc+2][m] = rA[i].z; As[kc+3][m] = rA[i].w;
        }
    };
    auto loadB = [&](int k0) {
        if (tid < 128) { int kr = tid >> 3, nc = (tid & 7) << 2;
            rB = *(const float4*)(Bb + (long)(k0 + kr) * N + (n0 + nc)); }
    };
    auto stoB = [&]() {
        if (tid < 128) { int kr = tid >> 3, nc = (tid & 7) << 2; *(float4*)&Bs[kr][nc] = rB; }
    };
    loadA(0); loadB(0); stoA(); stoB();
    __syncthreads();
    for (int k0 = BK; k0 < K + BK; k0 += BK) {
        bool more = (k0 < K);
        if (more) { loadA(k0); loadB(k0); }
#pragma unroll
        for (int kk = 0; kk < BK; kk++) {
            float a[TM], bv[TN];
#pragma unroll
            for (int i = 0; i < TM; i++) a[i] = As[kk][ty * TM + i];
#pragma unroll
            for (int j = 0; j < TN; j++) bv[j] = Bs[kk][tx * TN + j];
#pragma unroll
            for (int i = 0; i < TM; i++)
#pragma unroll
                for (int j = 0; j < TN; j++) acc[i][j] += a[i] * bv[j];
        }
        __syncthreads();
        if (more) { stoA(); stoB(); __syncthreads(); }
    }
#pragma unroll
    for (int i = 0; i < TM; i++) {
        int m = m0 + ty * TM + i;
#pragma unroll
        for (int j = 0; j < TN; j++) Cb[(long)m * N + n0 + tx * TN + j] = acc[i][j];
    }
}

// ---------------- reduce helpers ----------------
__device__ __forceinline__ float wmax(float v) {
#pragma unroll
    for (int o = 16; o; o >>= 1) v = fmaxf(v, __shfl_xor_sync(~0u, v, o));
    return v;
}
__device__ __forceinline__ float wsum(float v) {
#pragma unroll
    for (int o = 16; o; o >>= 1) v += __shfl_xor_sync(~0u, v, o);
    return v;
}

// ---------------- elementwise / im2col ----------------
__global__ void k_cvt(const float* __restrict__ s, __nv_bfloat16* __restrict__ h,
                      __nv_bfloat16* __restrict__ l, int n) {
    int i = blockIdx.x * 256 + threadIdx.x;
    if (i < n) { __nv_bfloat16 a, b; bsplit(s[i], a, b); h[i] = a; l[i] = b; }
}
__global__ void k_pack_w1(const float* __restrict__ Wq, const float* __restrict__ bq,
                          const float* __restrict__ Wk, const float* __restrict__ bk,
                          const float* __restrict__ Wv, const float* __restrict__ bv) {
    int idx = blockIdx.x * 256 + threadIdx.x;
    float v;
    if (idx < 65536) v = Wq[idx];
    else if (idx < 131072) v = Wk[idx - 65536];
    else v = Wv[idx - 131072];
    __nv_bfloat16 a, b; bsplit(v, a, b);
    g_W1h[idx] = a; g_W1l[idx] = b;
    if (idx < 64) g_b1[idx] = bq[idx];
    else if (idx < 128) g_b1[idx] = bk[idx - 64];
    else if (idx < 384) g_b1[idx] = bv[idx - 128];
}
__global__ void k_im2col1(const float* __restrict__ x) {
    __shared__ float t[32][33];
    int k0 = blockIdx.x * 32, n0 = blockIdx.y * 32;
    int tx = threadIdx.x;
#pragma unroll
    for (int it = 0; it < 4; it++) {
        int ty = threadIdx.y + it * 8;
        int k = k0 + ty, n = n0 + tx;
        int c = k >> 2, ky = (k >> 1) & 1, kx = k & 1;
        int b = n >> 10, l = n & 1023, y = l >> 5, xq = l & 31;
        t[ty][tx] = x[(((b * 256 + c) * 64) + (y * 2 + ky)) * 64 + xq * 2 + kx];
    }
    __syncthreads();
#pragma unroll
    for (int it = 0; it < 4; it++) {
        int ty = threadIdx.y + it * 8;
        __nv_bfloat16 a, b; bsplit(t[tx][ty], a, b);
        long o = (long)(n0 + ty) * 1024 + k0 + tx;
        g_X1h[o] = a; g_X1l[o] = b;
    }
}
__global__ void k_im2col2() {
    __shared__ float t[32][33];
    int k0 = blockIdx.x * 32, n0 = blockIdx.y * 32;
    int tx = threadIdx.x;
#pragma unroll
    for (int it = 0; it < 4; it++) {
        int ty = threadIdx.y + it * 8;
        int k = k0 + ty, n = n0 + tx;
        int c = k / 9, tap = k - c * 9;
        int dy = tap / 3 - 1, dx = tap - (tap / 3) * 3 - 1;
        int b = n >> 10, l = n & 1023, y = l >> 5, xq = l & 31;
        int yy = y + dy, xx = xq + dx;
        float v = 0.f;
        if ((unsigned)yy < 32u && (unsigned)xx < 32u) v = g_OP[c * 8192 + b * 1024 + yy * 32 + xx];
        t[ty][tx] = v;
    }
    __syncthreads();
#pragma unroll
    for (int it = 0; it < 4; it++) {
        int ty = threadIdx.y + it * 8;
        __nv_bfloat16 a, b; bsplit(t[tx][ty], a, b);
        long o = (long)(n0 + ty) * 2304 + k0 + tx;
        g_X2h[o] = a; g_X2l[o] = b;
    }
}
__global__ void k_im2col3() {
    __shared__ float t[32][33];
    int k0 = blockIdx.x * 32, n0 = blockIdx.y * 32;
    int tx = threadIdx.x;
#pragma unroll
    for (int it = 0; it < 4; it++) {
        int ty = threadIdx.y + it * 8;
        int k = k0 + ty, n = n0 + tx;
        int cc = k / 9, tap = k - cc * 9;
        int dy = tap / 3 - 1, dx = tap - (tap / 3) * 3 - 1;
        int b = n >> 12, pix = n & 4095, Y = pix >> 6, X = pix & 63;
        int YY = Y + dy, XX = X + dx;
        float v = 0.f;
        if ((unsigned)YY < 64u && (unsigned)XX < 64u) {
            const float* src = (cc < 256) ? (g_outpos + ((b * 256 + cc) * 4096))
                                          : (g_outcha + ((b * 256 + cc - 256) * 4096));
            v = src[YY * 64 + XX];
        }
        t[ty][tx] = v;
    }
    __syncthreads();
#pragma unroll
    for (int it = 0; it < 4; it++) {
        int ty = threadIdx.y + it * 8;
        __nv_bfloat16 a, b; bsplit(t[tx][ty], a, b);
        size_t o = (size_t)(n0 + ty) * 4608 + k0 + tx;
        g_X3h[o] = a; g_X3l[o] = b;
    }
}
__global__ void k_pos_attn() {
    __shared__ float Ks[8][1024];
    int b = blockIdx.z, h = blockIdx.y, tid = threadIdx.x;
    for (int idx = tid; idx < 8192; idx += 256) {
        int d = idx >> 10, k = idx & 1023;
        Ks[d][k] = g_P1[(64 + h * 8 + d) * BL + b * 1024 + k];
    }
    __syncthreads();
    int warp = tid >> 5, lane = tid & 31;
    int qb = blockIdx.x * 64 + warp * 8;
    for (int qq = 0; qq < 8; qq++) {
        int q = qb + qq;
        float Q[8];
#pragma unroll
        for (int d = 0; d < 8; d++) Q[d] = g_P1[(h * 8 + d) * BL + b * 1024 + q];
        float s[32], mx = -1e30f;
#pragma unroll
        for (int i = 0; i < 32; i++) {
            int k = i * 32 + lane;
            float sc = 0.f;
#pragma unroll
            for (int d = 0; d < 8; d++) sc += Q[d] * Ks[d][k];
            sc *= 0.35355339059327373f;
            s[i] = sc; mx = fmaxf(mx, sc);
        }
        mx = wmax(mx);
        float sum = 0.f;
#pragma unroll
        for (int i = 0; i < 32; i++) { float e = __expf(s[i] - mx); s[i] = e; sum += e; }
        float inv = 1.0f / wsum(sum);
        float* out = g_Pattn + ((size_t)(b * 8 + h) * 1024 + q) * 1024;
#pragma unroll
        for (int i = 0; i < 32; i++) out[i * 32 + lane] = s[i] * inv;
    }
}
__global__ void k_vr_repack() {
    int idx = blockIdx.x * 256 + threadIdx.x;
    int d = idx & 31, k = (idx >> 5) & 1023, bh = idx >> 15;
    g_Vr[idx] = g_P1[(128 + (bh & 7) * 32 + d) * BL + (bh >> 3) * 1024 + k];
}
__global__ void k_op_repack() {
    int idx = blockIdx.x * 256 + threadIdx.x;
    int n = idx & 8191, c = idx >> 13;
    int b = n >> 10, l = n & 1023;
    g_OP[idx] = g_O1[((b * 8 + (c >> 5)) * 1024 + l) * 32 + (c & 31)];
}
__global__ void k_upsample_residual(const float* __restrict__ x, const float* __restrict__ gamma) {
    int idx = blockIdx.x * 256 + threadIdx.x;
    int pix = idx & 4095, c = (idx >> 12) & 255, b = idx >> 20;
    int Y = pix >> 6, X = pix & 63;
    float sy = Y * 0.5f - 0.25f, sx = X * 0.5f - 0.25f;
    int y0 = (int)floorf(sy); float fy = sy - y0;
    int x0 = (int)floorf(sx); float fx = sx - x0;
    int y1 = min(y0 + 1, 31); y0 = max(y0, 0);
    int x1 = min(x0 + 1, 31); x0 = max(x0, 0);
    const float* p = g_O2 + c * 8192 + b * 1024;
    float v = (1.f - fy) * ((1.f - fx) * p[y0*32+x0] + fx * p[y0*32+x1])
            + fy * ((1.f - fx) * p[y1*32+x0] + fx * p[y1*32+x1]);
    g_outpos[idx] = x[idx] + gamma[0] * v;
}
__global__ void k_cha_proj(const float* __restrict__ x,
                           const float* __restrict__ Wq, const float* __restrict__ bq,
                           const float* __restrict__ Wk, const float* __restrict__ bk,
                           const float* __restrict__ Wv, const float* __restrict__ bv) {
    int l = blockIdx.x * 256 + threadIdx.x;
    int g = blockIdx.y, b = blockIdx.z;
    int i = l >> 5, j = l & 31;
    const float* xp = x + ((b * 256 + g) * 64) * 64;
    float x00 = xp[2*i*64 + 2*j], x01 = xp[2*i*64 + 2*j + 1];
    float x10 = xp[(2*i+1)*64 + 2*j], x11 = xp[(2*i+1)*64 + 2*j + 1];
    int base = (b * 2048 + g * 8) * 1024 + l;
#pragma unroll
    for (int h = 0; h < 8; h++) {
        int w = (g * 8 + h) * 4, o = base + h * 1024;
        float qv = Wq[w]*x00 + Wq[w+1]*x01 + Wq[w+2]*x10 + Wq[w+3]*x11 + bq[g*8+h];
        float kv = Wk[w]*x00 + Wk[w+1]*x01 + Wk[w+2]*x10 + Wk[w+3]*x11 + bk[g*8+h];
        float vv = Wv[w]*x00 + Wv[w+1]*x01 + Wv[w+2]*x10 + Wv[w+3]*x11 + bv[g*8+h];
        __nv_bfloat16 a, c;
        bsplit(qv, a, c); g_qch[o] = a; g_qcl[o] = c;
        bsplit(kv, a, c); g_kch[o] = a; g_kcl[o] = c;
        g_vc[o] = vv;
    }
}
__global__ void k_vcT() {
    __shared__ float t[32][33];
    int z = blockIdx.z, c0 = blockIdx.x * 32, l0 = blockIdx.y * 32;
    int tx = threadIdx.x;
    const float* src = g_vc + (long)z * 262144;
#pragma unroll
    for (int it = 0; it < 4; it++) {
        int ty = threadIdx.y + it * 8;
        t[ty][tx] = src[(c0 + ty) * 1024 + l0 + tx];
    }
    __syncthreads();
#pragma unroll
    for (int it = 0; it < 4; it++) {
        int ty = threadIdx.y + it * 8;
        __nv_bfloat16 a, b; bsplit(t[tx][ty], a, b);
        long o = (long)z * 262144 + (long)(l0 + ty) * 256 + c0 + tx;
        g_vTh[o] = a; g_vTl[o] = b;
    }
}
__global__ void k_cha_softmax() {
    int row = blockIdx.x * 8 + (threadIdx.x >> 5);
    int lane = threadIdx.x & 31;
    const float* r = g_Sc + (long)row * 256;
    float v[8], mx = -1e30f;
#pragma unroll
    for (int j = 0; j < 8; j++) { v[j] = r[j * 32 + lane] * 0.03125f; mx = fmaxf(mx, v[j]); }
    mx = wmax(mx);
    float sum = 0.f;
#pragma unroll
    for (int j = 0; j < 8; j++) { v[j] = __expf(v[j] - mx); sum += v[j]; }
    float inv = 1.0f / wsum(sum);
#pragma unroll
    for (int j = 0; j < 8; j++) {
        __nv_bfloat16 a, b; bsplit(v[j] * inv, a, b);
        long o = (long)row * 256 + j * 32 + lane;
        g_Pch[o] = a; g_Pcl[o] = b;
    }
}
__global__ void k_ct_residual(const float* __restrict__ x, const float* __restrict__ Wt,
                              const float* __restrict__ bt, const float* __restrict__ gamma) {
    int pix = blockIdx.x * 256 + threadIdx.x;
    int g = blockIdx.y, b = blockIdx.z;
    int Y = pix >> 6, X = pix & 63;
    int p = Y >> 1, ky = Y & 1, q = X >> 1, kx = X & 1;
    float s = bt[g];
    int ob = (b * 2048 + g * 8) * 1024 + p * 32 + q;
#pragma unroll
    for (int i = 0; i < 8; i++) s += g_oc[ob + i * 1024] * Wt[(g * 8 + i) * 4 + ky * 2 + kx];
    int idx = ((b * 256 + g) * 4096) + pix;
    g_outcha[idx] = x[idx] + gamma[0] * s;
}
__global__ void k_out_permute(float* __restrict__ out) {
    int idx = blockIdx.x * 256 + threadIdx.x;
    int pix = idx & 4095, ocb = idx >> 12;
    out[idx] = g_O3[(ocb & 255) * 32768 + (ocb >> 8) * 4096 + pix];
}

// ---------------- launch ----------------
static void* sym(const void* s) { void* p = nullptr; cudaGetSymbolAddress(&p, s); return p; }

extern "C" void kernel_launch(void* const* d_in, const int* in_sizes, int n_in,
                              void* d_out, int out_size) {
    const float *qkv_pos = (const float*)d_in[0], *qkv_cha = (const float*)d_in[1];
    const float *Wq_pos = (const float*)d_in[2], *bq_pos = (const float*)d_in[3];
    const float *Wk_pos = (const float*)d_in[4], *bk_pos = (const float*)d_in[5];
    const float *Wv_pos = (const float*)d_in[6], *bv_pos = (const float*)d_in[7];
    const float *Wo_pos = (const float*)d_in[8], *bo_pos = (const float*)d_in[9];
    const float *gamma_pos = (const float*)d_in[10];
    const float *Wq_cha = (const float*)d_in[11], *bq_cha = (const float*)d_in[12];
    const float *Wk_cha = (const float*)d_in[13], *bk_cha = (const float*)d_in[14];
    const float *Wv_cha = (const float*)d_in[15], *bv_cha = (const float*)d_in[16];
    const float *Wt_cha = (const float*)d_in[17], *bt_cha = (const float*)d_in[18];
    const float *gamma_cha = (const float*)d_in[19];
    const float *Wf = (const float*)d_in[20], *bf = (const float*)d_in[21];
    float* out = (float*)d_out;

    static int inited = 0;
    if (!inited) {
        cudaFuncSetAttribute(tgemm, cudaFuncAttributeMaxDynamicSharedMemorySize, TSMEM);
        inited = 1;
    }

    __nv_bfloat16 *pW1h = (__nv_bfloat16*)sym(g_W1h), *pW1l = (__nv_bfloat16*)sym(g_W1l);
    __nv_bfloat16 *pX1h = (__nv_bfloat16*)sym(g_X1h), *pX1l = (__nv_bfloat16*)sym(g_X1l);
    __nv_bfloat16 *pWoh = (__nv_bfloat16*)sym(g_Woh), *pWol = (__nv_bfloat16*)sym(g_Wol);
    __nv_bfloat16 *pX2h = (__nv_bfloat16*)sym(g_X2h), *pX2l = (__nv_bfloat16*)sym(g_X2l);
    __nv_bfloat16 *pWfh = (__nv_bfloat16*)sym(g_Wfh), *pWfl = (__nv_bfloat16*)sym(g_Wfl);
    __nv_bfloat16 *pX3h = (__nv_bfloat16*)sym(g_X3h), *pX3l = (__nv_bfloat16*)sym(g_X3l);
    __nv_bfloat16 *pqch = (__nv_bfloat16*)sym(g_qch), *pqcl = (__nv_bfloat16*)sym(g_qcl);
    __nv_bfloat16 *pkch = (__nv_bfloat16*)sym(g_kch), *pkcl = (__nv_bfloat16*)sym(g_kcl);
    __nv_bfloat16 *pvTh = (__nv_bfloat16*)sym(g_vTh), *pvTl = (__nv_bfloat16*)sym(g_vTl);
    __nv_bfloat16 *pPch = (__nv_bfloat16*)sym(g_Pch), *pPcl = (__nv_bfloat16*)sym(g_Pcl);
    float *pb1 = (float*)sym(g_b1), *pP1 = (float*)sym(g_P1);
    float *pPattn = (float*)sym(g_Pattn), *pVr = (float*)sym(g_Vr), *pO1 = (float*)sym(g_O1);
    float *pO2 = (float*)sym(g_O2), *pSc = (float*)sym(g_Sc), *poc = (float*)sym(g_oc);
    float *pO3 = (float*)sym(g_O3);

    // ---- POS ----
    k_pack_w1<<<1536, 256>>>(Wq_pos, bq_pos, Wk_pos, bk_pos, Wv_pos, bv_pos);
    k_im2col1<<<dim3(32, 256), dim3(32, 8)>>>(qkv_pos);
    tgemm<<<dim3(64, 3, 1), 256, TSMEM>>>(pW1h, pW1l, pX1h, pX1l, pP1, pb1, 8192, 1024, 0, 0, 0);
    k_pos_attn<<<dim3(16, 8, 8), 256>>>();
    k_vr_repack<<<8192, 256>>>();
    sgemm32<<<dim3(1, 8, 64), 256>>>(pPattn, pVr, pO1, 32, 1024, 1048576L, 32768L, 32768L);
    k_op_repack<<<8192, 256>>>();
    k_cvt<<<2304, 256>>>(Wo_pos, pWoh, pWol, 256 * 2304);
    k_im2col2<<<dim3(72, 256), dim3(32, 8)>>>();
    tgemm<<<dim3(64, 2, 1), 256, TSMEM>>>(pWoh, pWol, pX2h, pX2l, pO2, bo_pos, 8192, 2304, 0, 0, 0);
    k_upsample_residual<<<32768, 256>>>(qkv_pos, gamma_pos);

    // ---- CHA ----
    k_cha_proj<<<dim3(4, 256, 8), 256>>>(qkv_cha, Wq_cha, bq_cha, Wk_cha, bk_cha, Wv_cha, bv_cha);
    k_vcT<<<dim3(8, 32, 64), dim3(32, 8)>>>();
    tgemm<<<dim3(2, 2, 64), 256, TSMEM>>>(pqch, pqcl, pkch, pkcl, pSc, nullptr, 256, 1024, 262144L, 262144L, 65536L);
    k_cha_softmax<<<2048, 256>>>();
    tgemm<<<dim3(8, 2, 64), 256, TSMEM>>>(pPch, pPcl, pvTh, pvTl, poc, nullptr, 1024, 256, 65536L, 262144L, 262144L);
    k_ct_residual<<<dim3(16, 256, 8), 256>>>(qkv_cha, Wt_cha, bt_cha, gamma_cha);

    // ---- fusion ----
    k_cvt<<<4608, 256>>>(Wf, pWfh, pWfl, 256 * 4608);
    k_im2col3<<<dim3(144, 1024), dim3(32, 8)>>>();
    tgemm<<<dim3(256, 2, 1), 256, TSMEM>>>(pWfh, pWfl, pX3h, pX3l, pO3, bf, 32768, 4608, 0, 0, 0);
    k_out_permute<<<32768, 256>>>(out);
}

// round 5
// speedup vs baseline: 1.9615x; 1.1282x over previous
#include <cuda_runtime.h>
#include <cuda_bf16.h>
#include <math.h>
#include <stdint.h>

#define Bz 8
#define BL 8192

__device__ __forceinline__ uint32_t smem_u32(const void* p) {
    uint32_t a;
    asm("{ .reg .u64 t; cvta.to.shared.u64 t, %1; cvt.u32.u64 %0, t; }" : "=r"(a) : "l"(p));
    return a;
}
__device__ __forceinline__ void cp16(uint32_t s, const void* g) {
    unsigned long long ga = (unsigned long long)__cvta_generic_to_global(g);
    asm volatile("cp.async.cg.shared.global [%0], [%1], 16;" :: "r"(s), "l"(ga));
}
__device__ __forceinline__ void ldsm4(uint32_t* r, uint32_t a) {
    asm volatile("ldmatrix.sync.aligned.m8n8.x4.shared.b16 {%0,%1,%2,%3}, [%4];"
                 : "=r"(r[0]), "=r"(r[1]), "=r"(r[2]), "=r"(r[3]) : "r"(a));
}
__device__ __forceinline__ void mma16816(float* c, const uint32_t* a, const uint32_t* b) {
    asm volatile("mma.sync.aligned.m16n8k16.row.col.f32.bf16.bf16.f32 "
                 "{%0,%1,%2,%3}, {%4,%5,%6,%7}, {%8,%9}, {%0,%1,%2,%3};"
                 : "+f"(c[0]), "+f"(c[1]), "+f"(c[2]), "+f"(c[3])
                 : "r"(a[0]), "r"(a[1]), "r"(a[2]), "r"(a[3]), "r"(b[0]), "r"(b[1]));
}
__device__ __forceinline__ void bsplit(float v, __nv_bfloat16& h, __nv_bfloat16& l) {
    h = __float2bfloat16(v);
    l = __float2bfloat16(v - __bfloat162float(h));
}

// ---------------- scratch ----------------
#define AL __align__(256)
__device__ AL __nv_bfloat16 g_W1h[384*1024], g_W1l[384*1024];
__device__ float g_b1[384];
__device__ AL __nv_bfloat16 g_X1h[8192*1024], g_X1l[8192*1024];
__device__ float g_P1[384*8192];
__device__ float g_Pattn[(size_t)64*1024*1024];
__device__ float g_Vr[64*1024*32];
__device__ float g_O1[64*1024*32];
__device__ AL __nv_bfloat16 g_Woh[256*2304], g_Wol[256*2304];    // tap-major reorder
__device__ AL __nv_bfloat16 g_I2h[8*34*34*256], g_I2l[8*34*34*256]; // padded ch-last attn-out
__device__ float g_O2[256*8192];
__device__ float g_outpos[8*256*4096];
__device__ AL __nv_bfloat16 g_qch[8*2048*1024], g_qcl[8*2048*1024];
__device__ AL __nv_bfloat16 g_kch[8*2048*1024], g_kcl[8*2048*1024];
__device__ float g_vc[8*2048*1024];
__device__ AL __nv_bfloat16 g_vTh[64*1024*256], g_vTl[64*1024*256];
__device__ float g_Sc[64*256*256];
__device__ AL __nv_bfloat16 g_Pch[64*256*256], g_Pcl[64*256*256];
__device__ float g_oc[8*2048*1024];
__device__ float g_outcha[8*256*4096];
__device__ AL __nv_bfloat16 g_Wfh[256*4608], g_Wfl[256*4608];    // tap-major reorder
__device__ AL __nv_bfloat16 g_I3h[8*66*66*512], g_I3l[8*66*66*512]; // padded ch-last fusion in
__device__ float g_O3[256*32768];

// ========= mma.sync split-bf16 GEMM (plain, row-major B) =========
#define PITCHB 80
#define TSZ 10240
#define STGSZ 40960
#define TSMEM (2*STGSZ)

__global__ __launch_bounds__(256) void tgemm(
    const __nv_bfloat16* __restrict__ Ah, const __nv_bfloat16* __restrict__ Al,
    const __nv_bfloat16* __restrict__ Bh, const __nv_bfloat16* __restrict__ Bl,
    float* __restrict__ C, const float* __restrict__ bias,
    int N, int K, long sA, long sB, long sC)
{
    extern __shared__ __align__(128) char smem_raw[];
    const uint32_t sb = smem_u32(smem_raw);
    const int tid = threadIdx.x, wid = tid >> 5, lane = tid & 31;
    const int wm = wid >> 2, wn = wid & 3;
    const int m0 = blockIdx.y * 128, n0 = blockIdx.x * 128;

    const __nv_bfloat16* gp[4] = {
        Ah + (long)blockIdx.z * sA + (long)m0 * K,
        Al + (long)blockIdx.z * sA + (long)m0 * K,
        Bh + (long)blockIdx.z * sB + (long)n0 * K,
        Bl + (long)blockIdx.z * sB + (long)n0 * K };

    const int lg = lane >> 3, l8 = lane & 7;
    const int row_off = l8 + (lg & 1) * 8;
    const int kadd = (lg >> 1) * 8;
    const int rowA = wm * 64 + row_off;
    const int rowB = wn * 32 + row_off;

    float acc[4][4][4];
#pragma unroll
    for (int a = 0; a < 4; a++)
#pragma unroll
        for (int b = 0; b < 4; b++)
#pragma unroll
            for (int c = 0; c < 4; c++) acc[a][b][c] = 0.f;

    const int nch = K >> 5;
    auto load_stage = [&](int ch, int st) {
        uint32_t base = sb + st * STGSZ;
        int k0 = ch << 5;
#pragma unroll
        for (int j = 0; j < 8; j++) {
            int id = tid + j * 256;
            int t = id >> 9, w = id & 511;
            int row = w >> 2, c16 = (w & 3);
            cp16(base + t * TSZ + row * PITCHB + c16 * 16,
                 gp[t] + (long)row * K + k0 + c16 * 8);
        }
        asm volatile("cp.async.commit_group;" ::: "memory");
    };

    load_stage(0, 0);
    for (int i = 0; i < nch; i++) {
        int st = i & 1;
        if (i + 1 < nch) {
            load_stage(i + 1, st ^ 1);
            asm volatile("cp.async.wait_group 1;" ::: "memory");
        } else {
            asm volatile("cp.async.wait_group 0;" ::: "memory");
        }
        __syncthreads();
        uint32_t sA_h = sb + st * STGSZ, sA_l = sA_h + TSZ;
        uint32_t sB_h = sA_h + 2 * TSZ, sB_l = sA_h + 3 * TSZ;
#pragma unroll
        for (int ks = 0; ks < 2; ks++) {
            uint32_t kb = (uint32_t)(ks * 16 + kadd) * 2;
            uint32_t bh[4][2], bl[4][2];
#pragma unroll
            for (int p = 0; p < 2; p++) {
                uint32_t r[4];
                ldsm4(r, sB_h + (uint32_t)(rowB + p * 16) * PITCHB + kb);
                bh[p*2][0] = r[0]; bh[p*2][1] = r[2];
                bh[p*2+1][0] = r[1]; bh[p*2+1][1] = r[3];
                ldsm4(r, sB_l + (uint32_t)(rowB + p * 16) * PITCHB + kb);
                bl[p*2][0] = r[0]; bl[p*2][1] = r[2];
                bl[p*2+1][0] = r[1]; bl[p*2+1][1] = r[3];
            }
#pragma unroll
            for (int mt = 0; mt < 4; mt++) {
                uint32_t ah[4], al[4];
                ldsm4(ah, sA_h + (uint32_t)(rowA + mt * 16) * PITCHB + kb);
                ldsm4(al, sA_l + (uint32_t)(rowA + mt * 16) * PITCHB + kb);
#pragma unroll
                for (int nt = 0; nt < 4; nt++) {
                    mma16816(acc[mt][nt], ah, bh[nt]);
                    mma16816(acc[mt][nt], ah, bl[nt]);
                    mma16816(acc[mt][nt], al, bh[nt]);
                }
            }
        }
        __syncthreads();
    }

    float* Cb = C + (long)blockIdx.z * sC;
#pragma unroll
    for (int mt = 0; mt < 4; mt++) {
        int m = m0 + wm * 64 + mt * 16 + (lane >> 2);
        float b0 = bias ? bias[m] : 0.f;
        float b1 = bias ? bias[m + 8] : 0.f;
#pragma unroll
        for (int nt = 0; nt < 4; nt++) {
            int n = n0 + wn * 32 + nt * 8 + (lane & 3) * 2;
            float2 v0 = { acc[mt][nt][0] + b0, acc[mt][nt][1] + b0 };
            float2 v1 = { acc[mt][nt][2] + b1, acc[mt][nt][3] + b1 };
            *(float2*)(Cb + (long)m * N + n) = v0;
            *(float2*)(Cb + (long)(m + 8) * N + n) = v1;
        }
    }
}

// ========= direct-conv variant: B gathered from padded channels-last image =========
// K is tap-major: k = tap*CH + c. Image: [b][PW][PW][CH] bf16, 1-px zero border.
// LW: log2 of output width (pixels per row). N = Bz << (2*LW).
template<int LW, int CH, int PW>
__global__ __launch_bounds__(256) void tgemm_conv(
    const __nv_bfloat16* __restrict__ Ah, const __nv_bfloat16* __restrict__ Al,
    const __nv_bfloat16* __restrict__ Ih, const __nv_bfloat16* __restrict__ Il,
    float* __restrict__ C, const float* __restrict__ bias, int N, int K)
{
    extern __shared__ __align__(128) char smem_raw[];
    const uint32_t sb = smem_u32(smem_raw);
    const int tid = threadIdx.x, wid = tid >> 5, lane = tid & 31;
    const int wm = wid >> 2, wn = wid & 3;
    const int m0 = blockIdx.y * 128, n0 = blockIdx.x * 128;

    const __nv_bfloat16* pA[2] = { Ah + (long)m0 * K, Al + (long)m0 * K };
    const __nv_bfloat16* pI[2] = { Ih, Il };
    constexpr int CPT = CH / 32;

    const int lg = lane >> 3, l8 = lane & 7;
    const int row_off = l8 + (lg & 1) * 8;
    const int kadd = (lg >> 1) * 8;
    const int rowA = wm * 64 + row_off;
    const int rowB = wn * 32 + row_off;

    float acc[4][4][4];
#pragma unroll
    for (int a = 0; a < 4; a++)
#pragma unroll
        for (int b = 0; b < 4; b++)
#pragma unroll
            for (int c = 0; c < 4; c++) acc[a][b][c] = 0.f;

    const int nch = K >> 5;
    auto load_stage = [&](int ch, int st) {
        uint32_t base = sb + st * STGSZ;
        int k0 = ch << 5;
        int tap = ch / CPT;
        int cc0 = (ch % CPT) << 5;
        int dyp = tap / 3, dxp = tap - dyp * 3;
#pragma unroll
        for (int j = 0; j < 8; j++) {
            int id = tid + j * 256;
            int t = id >> 9, w = id & 511;
            int row = w >> 2, c16 = (w & 3);
            uint32_t sa = base + t * TSZ + row * PITCHB + c16 * 16;
            if (t < 2) {
                cp16(sa, pA[t] + (long)row * K + k0 + c16 * 8);
            } else {
                int n = n0 + row;
                int b = n >> (2 * LW);
                int pix = n & ((1 << (2 * LW)) - 1);
                int Y = pix >> LW, X = pix & ((1 << LW) - 1);
                long off = ((long)((b * PW + Y + dyp) * PW) + X + dxp) * CH + cc0 + c16 * 8;
                cp16(sa, pI[t - 2] + off);
            }
        }
        asm volatile("cp.async.commit_group;" ::: "memory");
    };

    load_stage(0, 0);
    for (int i = 0; i < nch; i++) {
        int st = i & 1;
        if (i + 1 < nch) {
            load_stage(i + 1, st ^ 1);
            asm volatile("cp.async.wait_group 1;" ::: "memory");
        } else {
            asm volatile("cp.async.wait_group 0;" ::: "memory");
        }
        __syncthreads();
        uint32_t sA_h = sb + st * STGSZ, sA_l = sA_h + TSZ;
        uint32_t sB_h = sA_h + 2 * TSZ, sB_l = sA_h + 3 * TSZ;
#pragma unroll
        for (int ks = 0; ks < 2; ks++) {
            uint32_t kb = (uint32_t)(ks * 16 + kadd) * 2;
            uint32_t bh[4][2], bl[4][2];
#pragma unroll
            for (int p = 0; p < 2; p++) {
                uint32_t r[4];
                ldsm4(r, sB_h + (uint32_t)(rowB + p * 16) * PITCHB + kb);
                bh[p*2][0] = r[0]; bh[p*2][1] = r[2];
                bh[p*2+1][0] = r[1]; bh[p*2+1][1] = r[3];
                ldsm4(r, sB_l + (uint32_t)(rowB + p * 16) * PITCHB + kb);
                bl[p*2][0] = r[0]; bl[p*2][1] = r[2];
                bl[p*2+1][0] = r[1]; bl[p*2+1][1] = r[3];
            }
#pragma unroll
            for (int mt = 0; mt < 4; mt++) {
                uint32_t ah[4], al[4];
                ldsm4(ah, sA_h + (uint32_t)(rowA + mt * 16) * PITCHB + kb);
                ldsm4(al, sA_l + (uint32_t)(rowA + mt * 16) * PITCHB + kb);
#pragma unroll
                for (int nt = 0; nt < 4; nt++) {
                    mma16816(acc[mt][nt], ah, bh[nt]);
                    mma16816(acc[mt][nt], ah, bl[nt]);
                    mma16816(acc[mt][nt], al, bh[nt]);
                }
            }
        }
        __syncthreads();
    }

#pragma unroll
    for (int mt = 0; mt < 4; mt++) {
        int m = m0 + wm * 64 + mt * 16 + (lane >> 2);
        float b0 = bias ? bias[m] : 0.f;
        float b1 = bias ? bias[m + 8] : 0.f;
#pragma unroll
        for (int nt = 0; nt < 4; nt++) {
            int n = n0 + wn * 32 + nt * 8 + (lane & 3) * 2;
            float2 v0 = { acc[mt][nt][0] + b0, acc[mt][nt][1] + b0 };
            float2 v1 = { acc[mt][nt][2] + b1, acc[mt][nt][3] + b1 };
            *(float2*)(C + (long)m * N + n) = v0;
            *(float2*)(C + (long)(m + 8) * N + n) = v1;
        }
    }
}

// ================= fp32 SGEMM (pos P@V, N=32) =================
__global__ __launch_bounds__(256) void sgemm32(
    const float* __restrict__ A, const float* __restrict__ B, float* __restrict__ C,
    int N, int K, long sA, long sB, long sC)
{
    constexpr int BM = 128, BK = 16, BN = 32, TM = 8, TN = 2;
    __shared__ float As[BK][BM + 4];
    __shared__ float Bs[BK][BN];
    const float* Ab = A + (long)blockIdx.z * sA;
    const float* Bb = B + (long)blockIdx.z * sB;
    float* Cb = C + (long)blockIdx.z * sC;
    const int m0 = blockIdx.y * BM, n0 = blockIdx.x * BN;
    const int tid = threadIdx.x, tx = tid & 15, ty = tid >> 4;
    float acc[TM][TN] = {};
    float4 rA[2]; float4 rB;
    auto loadA = [&](int k0) {
#pragma unroll
        for (int i = 0; i < 2; i++) {
            int f = tid + i * 256, m = f >> 2, kc = (f & 3) << 2;
            rA[i] = *(const float4*)(Ab + (long)(m0 + m) * K + (k0 + kc));
        }
    };
    auto stoA = [&]() {
#pragma unroll
        for (int i = 0; i < 2; i++) {
            int f = tid + i * 256, m = f >> 2, kc = (f & 3) << 2;
            As[kc][m] = rA[i].x; As[kc+1][m] = rA[i].y; As[kc+2][m] = rA[i].z; As[kc+3][m] = rA[i].w;
        }
    };
    auto loadB = [&](int k0) {
        if (tid < 128) { int kr = tid >> 3, nc = (tid & 7) << 2;
            rB = *(const float4*)(Bb + (long)(k0 + kr) * N + (n0 + nc)); }
    };
    auto stoB = [&]() {
        if (tid < 128) { int kr = tid >> 3, nc = (tid & 7) << 2; *(float4*)&Bs[kr][nc] = rB; }
    };
    loadA(0); loadB(0); stoA(); stoB();
    __syncthreads();
    for (int k0 = BK; k0 < K + BK; k0 += BK) {
        bool more = (k0 < K);
        if (more) { loadA(k0); loadB(k0); }
#pragma unroll
        for (int kk = 0; kk < BK; kk++) {
            float a[TM], bv[TN];
#pragma unroll
            for (int i = 0; i < TM; i++) a[i] = As[kk][ty * TM + i];
#pragma unroll
            for (int j = 0; j < TN; j++) bv[j] = Bs[kk][tx * TN + j];
#pragma unroll
            for (int i = 0; i < TM; i++)
#pragma unroll
                for (int j = 0; j < TN; j++) acc[i][j] += a[i] * bv[j];
        }
        __syncthreads();
        if (more) { stoA(); stoB(); __syncthreads(); }
    }
#pragma unroll
    for (int i = 0; i < TM; i++) {
        int m = m0 + ty * TM + i;
#pragma unroll
        for (int j = 0; j < TN; j++) Cb[(long)m * N + n0 + tx * TN + j] = acc[i][j];
    }
}

// ---------------- reduce helpers ----------------
__device__ __forceinline__ float wmax(float v) {
#pragma unroll
    for (int o = 16; o; o >>= 1) v = fmaxf(v, __shfl_xor_sync(~0u, v, o));
    return v;
}
__device__ __forceinline__ float wsum(float v) {
#pragma unroll
    for (int o = 16; o; o >>= 1) v += __shfl_xor_sync(~0u, v, o);
    return v;
}

// ---------------- small kernels ----------------
__global__ void k_zero4(float4* p, int n4) {
    int i = blockIdx.x * 256 + threadIdx.x;
    if (i < n4) p[i] = make_float4(0.f, 0.f, 0.f, 0.f);
}
// weight tap-major reorder + split: src [OC][CIN*9] (k=cc*9+tap) -> dst k=tap*CIN+cc
__global__ void k_wrd(const float* __restrict__ W, __nv_bfloat16* __restrict__ h,
                      __nv_bfloat16* __restrict__ l, int CIN) {
    int idx = blockIdx.x * 256 + threadIdx.x;   // OC*CIN*9 total
    int K = CIN * 9;
    int oc = idx / K, rem = idx - oc * K;
    int cc = rem / 9, tap = rem - cc * 9;
    __nv_bfloat16 a, b; bsplit(W[idx], a, b);
    long d = (long)oc * K + tap * CIN + cc;
    h[d] = a; l[d] = b;
}
__global__ void k_pack_w1(const float* __restrict__ Wq, const float* __restrict__ bq,
                          const float* __restrict__ Wk, const float* __restrict__ bk,
                          const float* __restrict__ Wv, const float* __restrict__ bv) {
    int idx = blockIdx.x * 256 + threadIdx.x;
    float v;
    if (idx < 65536) v = Wq[idx];
    else if (idx < 131072) v = Wk[idx - 65536];
    else v = Wv[idx - 131072];
    __nv_bfloat16 a, b; bsplit(v, a, b);
    g_W1h[idx] = a; g_W1l[idx] = b;
    if (idx < 64) g_b1[idx] = bq[idx];
    else if (idx < 128) g_b1[idx] = bk[idx - 64];
    else if (idx < 384) g_b1[idx] = bv[idx - 128];
}
__global__ void k_im2col1(const float* __restrict__ x) {
    __shared__ float t[32][33];
    int k0 = blockIdx.x * 32, n0 = blockIdx.y * 32;
    int tx = threadIdx.x;
#pragma unroll
    for (int it = 0; it < 4; it++) {
        int ty = threadIdx.y + it * 8;
        int k = k0 + ty, n = n0 + tx;
        int c = k >> 2, ky = (k >> 1) & 1, kx = k & 1;
        int b = n >> 10, l = n & 1023, y = l >> 5, xq = l & 31;
        t[ty][tx] = x[(((b * 256 + c) * 64) + (y * 2 + ky)) * 64 + xq * 2 + kx];
    }
    __syncthreads();
#pragma unroll
    for (int it = 0; it < 4; it++) {
        int ty = threadIdx.y + it * 8;
        __nv_bfloat16 a, b; bsplit(t[tx][ty], a, b);
        long o = (long)(n0 + ty) * 1024 + k0 + tx;
        g_X1h[o] = a; g_X1l[o] = b;
    }
}
__global__ void k_pos_attn() {
    __shared__ float Ks[8][1024];
    int b = blockIdx.z, h = blockIdx.y, tid = threadIdx.x;
    for (int idx = tid; idx < 8192; idx += 256) {
        int d = idx >> 10, k = idx & 1023;
        Ks[d][k] = g_P1[(64 + h * 8 + d) * BL + b * 1024 + k];
    }
    __syncthreads();
    int warp = tid >> 5, lane = tid & 31;
    int qb = blockIdx.x * 64 + warp * 8;
#pragma unroll 1
    for (int qq = 0; qq < 8; qq++) {
        int q = qb + qq;
        float Q[8];
#pragma unroll
        for (int d = 0; d < 8; d++) Q[d] = g_P1[(h * 8 + d) * BL + b * 1024 + q];
        float s[32], mx = -1e30f;
#pragma unroll
        for (int i = 0; i < 32; i++) {
            int k = i * 32 + lane;
            float sc = 0.f;
#pragma unroll
            for (int d = 0; d < 8; d++) sc += Q[d] * Ks[d][k];
            sc *= 0.35355339059327373f;
            s[i] = sc; mx = fmaxf(mx, sc);
        }
        mx = wmax(mx);
        float sum = 0.f;
#pragma unroll
        for (int i = 0; i < 32; i++) { float e = __expf(s[i] - mx); s[i] = e; sum += e; }
        float inv = 1.0f / wsum(sum);
        float* out = g_Pattn + ((size_t)(b * 8 + h) * 1024 + q) * 1024;
#pragma unroll
        for (int i = 0; i < 32; i++) out[i * 32 + lane] = s[i] * inv;
    }
}
__global__ void k_vr_repack() {
    int idx = blockIdx.x * 256 + threadIdx.x;
    int d = idx & 31, k = (idx >> 5) & 1023, bh = idx >> 15;
    g_Vr[idx] = g_P1[(128 + (bh & 7) * 32 + d) * BL + (bh >> 3) * 1024 + k];
}
// pack attention out O1[bh][q][d] -> padded ch-last img2[b][1+y][1+x][h*32+d]
__global__ void k_o1pack() {
    int warp = threadIdx.x >> 5, lane = threadIdx.x & 31;
    int q = blockIdx.x * 8 + warp;
    int bh = blockIdx.y, b = bh >> 3, h = bh & 7;
    float v = g_O1[((long)bh * 1024 + q) * 32 + lane];
    __nv_bfloat16 a, c; bsplit(v, a, c);
    int y = q >> 5, x = q & 31;
    long o = ((long)(b * 34 + 1 + y) * 34 + 1 + x) * 256 + h * 32 + lane;
    g_I2h[o] = a; g_I2l[o] = c;
}
__global__ void k_upsample_residual(const float* __restrict__ x, const float* __restrict__ gamma) {
    int idx = blockIdx.x * 256 + threadIdx.x;
    int pix = idx & 4095, c = (idx >> 12) & 255, b = idx >> 20;
    int Y = pix >> 6, X = pix & 63;
    float sy = Y * 0.5f - 0.25f, sx = X * 0.5f - 0.25f;
    int y0 = (int)floorf(sy); float fy = sy - y0;
    int x0 = (int)floorf(sx); float fx = sx - x0;
    int y1 = min(y0 + 1, 31); y0 = max(y0, 0);
    int x1 = min(x0 + 1, 31); x0 = max(x0, 0);
    const float* p = g_O2 + c * 8192 + b * 1024;
    float v = (1.f - fy) * ((1.f - fx) * p[y0*32+x0] + fx * p[y0*32+x1])
            + fy * ((1.f - fx) * p[y1*32+x0] + fx * p[y1*32+x1]);
    g_outpos[idx] = x[idx] + gamma[0] * v;
}
__global__ void k_cha_proj(const float* __restrict__ x,
                           const float* __restrict__ Wq, const float* __restrict__ bq,
                           const float* __restrict__ Wk, const float* __restrict__ bk,
                           const float* __restrict__ Wv, const float* __restrict__ bv) {
    int l = blockIdx.x * 256 + threadIdx.x;
    int g = blockIdx.y, b = blockIdx.z;
    int i = l >> 5, j = l & 31;
    const float* xp = x + ((b * 256 + g) * 64) * 64;
    float x00 = xp[2*i*64 + 2*j], x01 = xp[2*i*64 + 2*j + 1];
    float x10 = xp[(2*i+1)*64 + 2*j], x11 = xp[(2*i+1)*64 + 2*j + 1];
    int base = (b * 2048 + g * 8) * 1024 + l;
#pragma unroll
    for (int h = 0; h < 8; h++) {
        int w = (g * 8 + h) * 4, o = base + h * 1024;
        float qv = Wq[w]*x00 + Wq[w+1]*x01 + Wq[w+2]*x10 + Wq[w+3]*x11 + bq[g*8+h];
        float kv = Wk[w]*x00 + Wk[w+1]*x01 + Wk[w+2]*x10 + Wk[w+3]*x11 + bk[g*8+h];
        float vv = Wv[w]*x00 + Wv[w+1]*x01 + Wv[w+2]*x10 + Wv[w+3]*x11 + bv[g*8+h];
        __nv_bfloat16 a, c;
        bsplit(qv, a, c); g_qch[o] = a; g_qcl[o] = c;
        bsplit(kv, a, c); g_kch[o] = a; g_kcl[o] = c;
        g_vc[o] = vv;
    }
}
__global__ void k_vcT() {
    __shared__ float t[32][33];
    int z = blockIdx.z, c0 = blockIdx.x * 32, l0 = blockIdx.y * 32;
    int tx = threadIdx.x;
    const float* src = g_vc + (long)z * 262144;
#pragma unroll
    for (int it = 0; it < 4; it++) {
        int ty = threadIdx.y + it * 8;
        t[ty][tx] = src[(c0 + ty) * 1024 + l0 + tx];
    }
    __syncthreads();
#pragma unroll
    for (int it = 0; it < 4; it++) {
        int ty = threadIdx.y + it * 8;
        __nv_bfloat16 a, b; bsplit(t[tx][ty], a, b);
        long o = (long)z * 262144 + (long)(l0 + ty) * 256 + c0 + tx;
        g_vTh[o] = a; g_vTl[o] = b;
    }
}
__global__ void k_cha_softmax() {
    int row = blockIdx.x * 8 + (threadIdx.x >> 5);
    int lane = threadIdx.x & 31;
    const float* r = g_Sc + (long)row * 256;
    float v[8], mx = -1e30f;
#pragma unroll
    for (int j = 0; j < 8; j++) { v[j] = r[j * 32 + lane] * 0.03125f; mx = fmaxf(mx, v[j]); }
    mx = wmax(mx);
    float sum = 0.f;
#pragma unroll
    for (int j = 0; j < 8; j++) { v[j] = __expf(v[j] - mx); sum += v[j]; }
    float inv = 1.0f / wsum(sum);
#pragma unroll
    for (int j = 0; j < 8; j++) {
        __nv_bfloat16 a, b; bsplit(v[j] * inv, a, b);
        long o = (long)row * 256 + j * 32 + lane;
        g_Pch[o] = a; g_Pcl[o] = b;
    }
}
__global__ void k_ct_residual(const float* __restrict__ x, const float* __restrict__ Wt,
                              const float* __restrict__ bt, const float* __restrict__ gamma) {
    int pix = blockIdx.x * 256 + threadIdx.x;
    int g = blockIdx.y, b = blockIdx.z;
    int Y = pix >> 6, X = pix & 63;
    int p = Y >> 1, ky = Y & 1, q = X >> 1, kx = X & 1;
    float s = bt[g];
    int ob = (b * 2048 + g * 8) * 1024 + p * 32 + q;
#pragma unroll
    for (int i = 0; i < 8; i++) s += g_oc[ob + i * 1024] * Wt[(g * 8 + i) * 4 + ky * 2 + kx];
    int idx = ((b * 256 + g) * 4096) + pix;
    g_outcha[idx] = x[idx] + gamma[0] * s;
}
// pack outpos/outcha [b][c][pix] fp32 -> padded ch-last img3[b][1+Y][1+X][c512] bf16 hi/lo
__global__ void k_imgpack() {
    __shared__ float t[32][33];
    int c0 = blockIdx.x * 32, p0 = blockIdx.y * 32, b = blockIdx.z;
    int tx = threadIdx.x;
#pragma unroll
    for (int it = 0; it < 4; it++) {
        int ty = threadIdx.y + it * 8;
        int c = c0 + ty;
        t[ty][tx] = (c < 256) ? g_outpos[((long)(b * 256 + c)) * 4096 + p0 + tx]
                              : g_outcha[((long)(b * 256 + c - 256)) * 4096 + p0 + tx];
    }
    __syncthreads();
#pragma unroll
    for (int it = 0; it < 4; it++) {
        int ty = threadIdx.y + it * 8;
        int pix = p0 + ty, c = c0 + tx;
        int Y = pix >> 6, X = pix & 63;
        __nv_bfloat16 a, bb; bsplit(t[tx][ty], a, bb);
        long o = ((long)(b * 66 + 1 + Y) * 66 + 1 + X) * 512 + c;
        g_I3h[o] = a; g_I3l[o] = bb;
    }
}
__global__ void k_out_permute(float* __restrict__ out) {
    int idx = blockIdx.x * 256 + threadIdx.x;
    int pix = idx & 4095, ocb = idx >> 12;
    out[idx] = g_O3[(ocb & 255) * 32768 + (ocb >> 8) * 4096 + pix];
}

// ---------------- launch ----------------
static void* sym(const void* s) { void* p = nullptr; cudaGetSymbolAddress(&p, s); return p; }

extern "C" void kernel_launch(void* const* d_in, const int* in_sizes, int n_in,
                              void* d_out, int out_size) {
    const float *qkv_pos = (const float*)d_in[0], *qkv_cha = (const float*)d_in[1];
    const float *Wq_pos = (const float*)d_in[2], *bq_pos = (const float*)d_in[3];
    const float *Wk_pos = (const float*)d_in[4], *bk_pos = (const float*)d_in[5];
    const float *Wv_pos = (const float*)d_in[6], *bv_pos = (const float*)d_in[7];
    const float *Wo_pos = (const float*)d_in[8], *bo_pos = (const float*)d_in[9];
    const float *gamma_pos = (const float*)d_in[10];
    const float *Wq_cha = (const float*)d_in[11], *bq_cha = (const float*)d_in[12];
    const float *Wk_cha = (const float*)d_in[13], *bk_cha = (const float*)d_in[14];
    const float *Wv_cha = (const float*)d_in[15], *bv_cha = (const float*)d_in[16];
    const float *Wt_cha = (const float*)d_in[17], *bt_cha = (const float*)d_in[18];
    const float *gamma_cha = (const float*)d_in[19];
    const float *Wf = (const float*)d_in[20], *bf = (const float*)d_in[21];
    float* out = (float*)d_out;

    cudaFuncSetAttribute(tgemm, cudaFuncAttributeMaxDynamicSharedMemorySize, TSMEM);
    cudaFuncSetAttribute(tgemm_conv<5,256,34>, cudaFuncAttributeMaxDynamicSharedMemorySize, TSMEM);
    cudaFuncSetAttribute(tgemm_conv<6,512,66>, cudaFuncAttributeMaxDynamicSharedMemorySize, TSMEM);

    __nv_bfloat16 *pW1h = (__nv_bfloat16*)sym(g_W1h), *pW1l = (__nv_bfloat16*)sym(g_W1l);
    __nv_bfloat16 *pX1h = (__nv_bfloat16*)sym(g_X1h), *pX1l = (__nv_bfloat16*)sym(g_X1l);
    __nv_bfloat16 *pWoh = (__nv_bfloat16*)sym(g_Woh), *pWol = (__nv_bfloat16*)sym(g_Wol);
    __nv_bfloat16 *pI2h = (__nv_bfloat16*)sym(g_I2h), *pI2l = (__nv_bfloat16*)sym(g_I2l);
    __nv_bfloat16 *pWfh = (__nv_bfloat16*)sym(g_Wfh), *pWfl = (__nv_bfloat16*)sym(g_Wfl);
    __nv_bfloat16 *pI3h = (__nv_bfloat16*)sym(g_I3h), *pI3l = (__nv_bfloat16*)sym(g_I3l);
    __nv_bfloat16 *pqch = (__nv_bfloat16*)sym(g_qch), *pqcl = (__nv_bfloat16*)sym(g_qcl);
    __nv_bfloat16 *pkch = (__nv_bfloat16*)sym(g_kch), *pkcl = (__nv_bfloat16*)sym(g_kcl);
    __nv_bfloat16 *pvTh = (__nv_bfloat16*)sym(g_vTh), *pvTl = (__nv_bfloat16*)sym(g_vTl);
    __nv_bfloat16 *pPch = (__nv_bfloat16*)sym(g_Pch), *pPcl = (__nv_bfloat16*)sym(g_Pcl);
    float *pb1 = (float*)sym(g_b1), *pP1 = (float*)sym(g_P1);
    float *pPattn = (float*)sym(g_Pattn), *pVr = (float*)sym(g_Vr), *pO1 = (float*)sym(g_O1);
    float *pO2 = (float*)sym(g_O2), *pSc = (float*)sym(g_Sc), *poc = (float*)sym(g_oc);
    float *pO3 = (float*)sym(g_O3);

    // zero padded images (borders must be 0; interior overwritten below)
    k_zero4<<<1156, 256>>>((float4*)pI2h, 295936);
    k_zero4<<<1156, 256>>>((float4*)pI2l, 295936);
    k_zero4<<<8712, 256>>>((float4*)pI3h, 2230272);
    k_zero4<<<8712, 256>>>((float4*)pI3l, 2230272);

    // ---- POS ----
    k_pack_w1<<<1536, 256>>>(Wq_pos, bq_pos, Wk_pos, bk_pos, Wv_pos, bv_pos);
    k_im2col1<<<dim3(32, 256), dim3(32, 8)>>>(qkv_pos);
    tgemm<<<dim3(64, 3, 1), 256, TSMEM>>>(pW1h, pW1l, pX1h, pX1l, pP1, pb1, 8192, 1024, 0, 0, 0);
    k_pos_attn<<<dim3(16, 8, 8), 256>>>();
    k_vr_repack<<<8192, 256>>>();
    sgemm32<<<dim3(1, 8, 64), 256>>>(pPattn, pVr, pO1, 32, 1024, 1048576L, 32768L, 32768L);
    k_o1pack<<<dim3(128, 64), 256>>>();
    k_wrd<<<2304, 256>>>(Wo_pos, pWoh, pWol, 256);
    tgemm_conv<5,256,34><<<dim3(64, 2), 256, TSMEM>>>(pWoh, pWol, pI2h, pI2l, pO2, bo_pos, 8192, 2304);
    k_upsample_residual<<<32768, 256>>>(qkv_pos, gamma_pos);

    // ---- CHA ----
    k_cha_proj<<<dim3(4, 256, 8), 256>>>(qkv_cha, Wq_cha, bq_cha, Wk_cha, bk_cha, Wv_cha, bv_cha);
    k_vcT<<<dim3(8, 32, 64), dim3(32, 8)>>>();
    tgemm<<<dim3(2, 2, 64), 256, TSMEM>>>(pqch, pqcl, pkch, pkcl, pSc, nullptr, 256, 1024, 262144L, 262144L, 65536L);
    k_cha_softmax<<<2048, 256>>>();
    tgemm<<<dim3(8, 2, 64), 256, TSMEM>>>(pPch, pPcl, pvTh, pvTl, poc, nullptr, 1024, 256, 65536L, 262144L, 262144L);
    k_ct_residual<<<dim3(16, 256, 8), 256>>>(qkv_cha, Wt_cha, bt_cha, gamma_cha);

    // ---- fusion (direct conv from padded channels-last image) ----
    k_imgpack<<<dim3(16, 128, 8), dim3(32, 8)>>>();
    k_wrd<<<4608, 256>>>(Wf, pWfh, pWfl, 512);
    tgemm_conv<6,512,66><<<dim3(256, 2), 256, TSMEM>>>(pWfh, pWfl, pI3h, pI3l, pO3, bf, 32768, 4608);
    k_out_permute<<<32768, 256>>>(out);
}

// round 6
// speedup vs baseline: 2.0868x; 1.0639x over previous
#include <cuda_runtime.h>
#include <cuda_bf16.h>
#include <math.h>
#include <stdint.h>

#define Bz 8
#define BL 8192

__device__ __forceinline__ uint32_t smem_u32(const void* p) {
    uint32_t a;
    asm("{ .reg .u64 t; cvta.to.shared.u64 t, %1; cvt.u32.u64 %0, t; }" : "=r"(a) : "l"(p));
    return a;
}
__device__ __forceinline__ void cp16(uint32_t s, const void* g) {
    unsigned long long ga = (unsigned long long)__cvta_generic_to_global(g);
    asm volatile("cp.async.cg.shared.global [%0], [%1], 16;" :: "r"(s), "l"(ga));
}
__device__ __forceinline__ void ldsm4(uint32_t* r, uint32_t a) {
    asm volatile("ldmatrix.sync.aligned.m8n8.x4.shared.b16 {%0,%1,%2,%3}, [%4];"
                 : "=r"(r[0]), "=r"(r[1]), "=r"(r[2]), "=r"(r[3]) : "r"(a));
}
__device__ __forceinline__ void mma16816(float* c, const uint32_t* a, const uint32_t* b) {
    asm volatile("mma.sync.aligned.m16n8k16.row.col.f32.bf16.bf16.f32 "
                 "{%0,%1,%2,%3}, {%4,%5,%6,%7}, {%8,%9}, {%0,%1,%2,%3};"
                 : "+f"(c[0]), "+f"(c[1]), "+f"(c[2]), "+f"(c[3])
                 : "r"(a[0]), "r"(a[1]), "r"(a[2]), "r"(a[3]), "r"(b[0]), "r"(b[1]));
}
__device__ __forceinline__ void bsplit(float v, __nv_bfloat16& h, __nv_bfloat16& l) {
    h = __float2bfloat16(v);
    l = __float2bfloat16(v - __bfloat162float(h));
}

// ---------------- scratch ----------------
#define AL __align__(256)
__device__ AL __nv_bfloat16 g_W1h[384*1024], g_W1l[384*1024];
__device__ float g_b1[384];
__device__ AL __nv_bfloat16 g_X1h[8192*1024], g_X1l[8192*1024];
__device__ float g_P1[384*8192];
__device__ AL __nv_bfloat16 g_Pph[(size_t)64*1024*1024], g_Ppl[(size_t)64*1024*1024];
__device__ AL __nv_bfloat16 g_vTph[64*32*1024], g_vTpl[64*32*1024];
__device__ float g_PV[64*32*1024];                               // [bh][d][q]
__device__ AL __nv_bfloat16 g_Woh[256*2304], g_Wol[256*2304];
__device__ AL __nv_bfloat16 g_I2h[8*34*34*256], g_I2l[8*34*34*256];
__device__ float g_O2[256*8192];
__device__ AL __nv_bfloat16 g_qch[8*2048*1024], g_qcl[8*2048*1024];
__device__ AL __nv_bfloat16 g_kch[8*2048*1024], g_kcl[8*2048*1024];
__device__ float g_vc[8*2048*1024];
__device__ AL __nv_bfloat16 g_vTh[64*1024*256], g_vTl[64*1024*256];
__device__ float g_Sc[64*256*256];
__device__ AL __nv_bfloat16 g_Pch[64*256*256], g_Pcl[64*256*256];
__device__ float g_oc[8*2048*1024];
__device__ AL __nv_bfloat16 g_Wfh[256*4608], g_Wfl[256*4608];
__device__ AL __nv_bfloat16 g_I3h[8*66*66*512], g_I3l[8*66*66*512];

// ========= mma.sync split-bf16 GEMM (128x128 tile) =========
#define PITCHB 80
#define TSZ 10240
#define STGSZ 40960
#define TSMEM (2*STGSZ)

__global__ __launch_bounds__(256) void tgemm(
    const __nv_bfloat16* __restrict__ Ah, const __nv_bfloat16* __restrict__ Al,
    const __nv_bfloat16* __restrict__ Bh, const __nv_bfloat16* __restrict__ Bl,
    float* __restrict__ C, const float* __restrict__ bias,
    int N, int K, long sA, long sB, long sC)
{
    extern __shared__ __align__(128) char smem_raw[];
    const uint32_t sb = smem_u32(smem_raw);
    const int tid = threadIdx.x, wid = tid >> 5, lane = tid & 31;
    const int wm = wid >> 2, wn = wid & 3;
    const int m0 = blockIdx.y * 128, n0 = blockIdx.x * 128;

    const __nv_bfloat16* gp[4] = {
        Ah + (long)blockIdx.z * sA + (long)m0 * K,
        Al + (long)blockIdx.z * sA + (long)m0 * K,
        Bh + (long)blockIdx.z * sB + (long)n0 * K,
        Bl + (long)blockIdx.z * sB + (long)n0 * K };

    const int lg = lane >> 3, l8 = lane & 7;
    const int row_off = l8 + (lg & 1) * 8;
    const int kadd = (lg >> 1) * 8;
    const int rowA = wm * 64 + row_off;
    const int rowB = wn * 32 + row_off;

    float acc[4][4][4];
#pragma unroll
    for (int a = 0; a < 4; a++)
#pragma unroll
        for (int b = 0; b < 4; b++)
#pragma unroll
            for (int c = 0; c < 4; c++) acc[a][b][c] = 0.f;

    const int nch = K >> 5;
    auto load_stage = [&](int ch, int st) {
        uint32_t base = sb + st * STGSZ;
        int k0 = ch << 5;
#pragma unroll
        for (int j = 0; j < 8; j++) {
            int id = tid + j * 256;
            int t = id >> 9, w = id & 511;
            int row = w >> 2, c16 = (w & 3);
            cp16(base + t * TSZ + row * PITCHB + c16 * 16,
                 gp[t] + (long)row * K + k0 + c16 * 8);
        }
        asm volatile("cp.async.commit_group;" ::: "memory");
    };

    load_stage(0, 0);
    for (int i = 0; i < nch; i++) {
        int st = i & 1;
        if (i + 1 < nch) {
            load_stage(i + 1, st ^ 1);
            asm volatile("cp.async.wait_group 1;" ::: "memory");
        } else {
            asm volatile("cp.async.wait_group 0;" ::: "memory");
        }
        __syncthreads();
        uint32_t sA_h = sb + st * STGSZ, sA_l = sA_h + TSZ;
        uint32_t sB_h = sA_h + 2 * TSZ, sB_l = sA_h + 3 * TSZ;
#pragma unroll
        for (int ks = 0; ks < 2; ks++) {
            uint32_t kb = (uint32_t)(ks * 16 + kadd) * 2;
            uint32_t bh[4][2], bl[4][2];
#pragma unroll
            for (int p = 0; p < 2; p++) {
                uint32_t r[4];
                ldsm4(r, sB_h + (uint32_t)(rowB + p * 16) * PITCHB + kb);
                bh[p*2][0] = r[0]; bh[p*2][1] = r[2];
                bh[p*2+1][0] = r[1]; bh[p*2+1][1] = r[3];
                ldsm4(r, sB_l + (uint32_t)(rowB + p * 16) * PITCHB + kb);
                bl[p*2][0] = r[0]; bl[p*2][1] = r[2];
                bl[p*2+1][0] = r[1]; bl[p*2+1][1] = r[3];
            }
#pragma unroll
            for (int mt = 0; mt < 4; mt++) {
                uint32_t ah[4], al[4];
                ldsm4(ah, sA_h + (uint32_t)(rowA + mt * 16) * PITCHB + kb);
                ldsm4(al, sA_l + (uint32_t)(rowA + mt * 16) * PITCHB + kb);
#pragma unroll
                for (int nt = 0; nt < 4; nt++) {
                    mma16816(acc[mt][nt], ah, bh[nt]);
                    mma16816(acc[mt][nt], ah, bl[nt]);
                    mma16816(acc[mt][nt], al, bh[nt]);
                }
            }
        }
        __syncthreads();
    }

    float* Cb = C + (long)blockIdx.z * sC;
#pragma unroll
    for (int mt = 0; mt < 4; mt++) {
        int m = m0 + wm * 64 + mt * 16 + (lane >> 2);
        float b0 = bias ? bias[m] : 0.f;
        float b1 = bias ? bias[m + 8] : 0.f;
#pragma unroll
        for (int nt = 0; nt < 4; nt++) {
            int n = n0 + wn * 32 + nt * 8 + (lane & 3) * 2;
            float2 v0 = { acc[mt][nt][0] + b0, acc[mt][nt][1] + b0 };
            float2 v1 = { acc[mt][nt][2] + b1, acc[mt][nt][3] + b1 };
            *(float2*)(Cb + (long)m * N + n) = v0;
            *(float2*)(Cb + (long)(m + 8) * N + n) = v1;
        }
    }
}

// ========= direct-conv variant =========
template<int LW, int CH, int PW, bool DIRECT>
__global__ __launch_bounds__(256) void tgemm_conv(
    const __nv_bfloat16* __restrict__ Ah, const __nv_bfloat16* __restrict__ Al,
    const __nv_bfloat16* __restrict__ Ih, const __nv_bfloat16* __restrict__ Il,
    float* __restrict__ C, const float* __restrict__ bias, int N, int K)
{
    extern __shared__ __align__(128) char smem_raw[];
    const uint32_t sb = smem_u32(smem_raw);
    const int tid = threadIdx.x, wid = tid >> 5, lane = tid & 31;
    const int wm = wid >> 2, wn = wid & 3;
    const int m0 = blockIdx.y * 128, n0 = blockIdx.x * 128;

    const __nv_bfloat16* pA[2] = { Ah + (long)m0 * K, Al + (long)m0 * K };
    const __nv_bfloat16* pI[2] = { Ih, Il };
    constexpr int CPT = CH / 32;

    const int lg = lane >> 3, l8 = lane & 7;
    const int row_off = l8 + (lg & 1) * 8;
    const int kadd = (lg >> 1) * 8;
    const int rowA = wm * 64 + row_off;
    const int rowB = wn * 32 + row_off;

    float acc[4][4][4];
#pragma unroll
    for (int a = 0; a < 4; a++)
#pragma unroll
        for (int b = 0; b < 4; b++)
#pragma unroll
            for (int c = 0; c < 4; c++) acc[a][b][c] = 0.f;

    const int nch = K >> 5;
    auto load_stage = [&](int ch, int st) {
        uint32_t base = sb + st * STGSZ;
        int k0 = ch << 5;
        int tap = ch / CPT;
        int cc0 = (ch % CPT) << 5;
        int dyp = tap / 3, dxp = tap - dyp * 3;
#pragma unroll
        for (int j = 0; j < 8; j++) {
            int id = tid + j * 256;
            int t = id >> 9, w = id & 511;
            int row = w >> 2, c16 = (w & 3);
            uint32_t sa = base + t * TSZ + row * PITCHB + c16 * 16;
            if (t < 2) {
                cp16(sa, pA[t] + (long)row * K + k0 + c16 * 8);
            } else {
                int n = n0 + row;
                int b = n >> (2 * LW);
                int pix = n & ((1 << (2 * LW)) - 1);
                int Y = pix >> LW, X = pix & ((1 << LW) - 1);
                long off = ((long)((b * PW + Y + dyp) * PW) + X + dxp) * CH + cc0 + c16 * 8;
                cp16(sa, pI[t - 2] + off);
            }
        }
        asm volatile("cp.async.commit_group;" ::: "memory");
    };

    load_stage(0, 0);
    for (int i = 0; i < nch; i++) {
        int st = i & 1;
        if (i + 1 < nch) {
            load_stage(i + 1, st ^ 1);
            asm volatile("cp.async.wait_group 1;" ::: "memory");
        } else {
            asm volatile("cp.async.wait_group 0;" ::: "memory");
        }
        __syncthreads();
        uint32_t sA_h = sb + st * STGSZ, sA_l = sA_h + TSZ;
        uint32_t sB_h = sA_h + 2 * TSZ, sB_l = sA_h + 3 * TSZ;
#pragma unroll
        for (int ks = 0; ks < 2; ks++) {
            uint32_t kb = (uint32_t)(ks * 16 + kadd) * 2;
            uint32_t bh[4][2], bl[4][2];
#pragma unroll
            for (int p = 0; p < 2; p++) {
                uint32_t r[4];
                ldsm4(r, sB_h + (uint32_t)(rowB + p * 16) * PITCHB + kb);
                bh[p*2][0] = r[0]; bh[p*2][1] = r[2];
                bh[p*2+1][0] = r[1]; bh[p*2+1][1] = r[3];
                ldsm4(r, sB_l + (uint32_t)(rowB + p * 16) * PITCHB + kb);
                bl[p*2][0] = r[0]; bl[p*2][1] = r[2];
                bl[p*2+1][0] = r[1]; bl[p*2+1][1] = r[3];
            }
#pragma unroll
            for (int mt = 0; mt < 4; mt++) {
                uint32_t ah[4], al[4];
                ldsm4(ah, sA_h + (uint32_t)(rowA + mt * 16) * PITCHB + kb);
                ldsm4(al, sA_l + (uint32_t)(rowA + mt * 16) * PITCHB + kb);
#pragma unroll
                for (int nt = 0; nt < 4; nt++) {
                    mma16816(acc[mt][nt], ah, bh[nt]);
                    mma16816(acc[mt][nt], ah, bl[nt]);
                    mma16816(acc[mt][nt], al, bh[nt]);
                }
            }
        }
        __syncthreads();
    }

#pragma unroll
    for (int mt = 0; mt < 4; mt++) {
        int m = m0 + wm * 64 + mt * 16 + (lane >> 2);
        float b0 = bias ? bias[m] : 0.f;
        float b1 = bias ? bias[m + 8] : 0.f;
#pragma unroll
        for (int nt = 0; nt < 4; nt++) {
            int n = n0 + wn * 32 + nt * 8 + (lane & 3) * 2;
            float2 v0 = { acc[mt][nt][0] + b0, acc[mt][nt][1] + b0 };
            float2 v1 = { acc[mt][nt][2] + b1, acc[mt][nt][3] + b1 };
            if (DIRECT) {
                long base0 = ((long)(n >> 12) << 20) + (n & 4095);
                *(float2*)(C + base0 + (long)m * 4096) = v0;
                *(float2*)(C + base0 + (long)(m + 8) * 4096) = v1;
            } else {
                *(float2*)(C + (long)m * N + n) = v0;
                *(float2*)(C + (long)(m + 8) * N + n) = v1;
            }
        }
    }
}

// ========= PV GEMM: per bh, C[32(d)][1024(q)] = Vt[32][1024k] · P[q][k]^T =========
#define PVATSZ 2560
#define PVBTSZ 20480
#define PVSTG 46080
#define PVSMEM (2*PVSTG)
__global__ __launch_bounds__(256) void tgemm_pv()
{
    extern __shared__ __align__(128) char smem_raw[];
    const uint32_t sb = smem_u32(smem_raw);
    const int tid = threadIdx.x, wid = tid >> 5, lane = tid & 31;
    const int n0 = blockIdx.x * 256;
    const int z = blockIdx.z;

    const __nv_bfloat16* pA[2] = { g_vTph + (long)z * 32768, g_vTpl + (long)z * 32768 };
    const __nv_bfloat16* pB[2] = { g_Pph + (size_t)z * 1048576, g_Ppl + (size_t)z * 1048576 };

    const int lg = lane >> 3, l8 = lane & 7;
    const int row_off = l8 + (lg & 1) * 8;
    const int kadd = (lg >> 1) * 8;
    const int rowB = wid * 32 + row_off;

    float acc[2][4][4];
#pragma unroll
    for (int a = 0; a < 2; a++)
#pragma unroll
        for (int b = 0; b < 4; b++)
#pragma unroll
            for (int c = 0; c < 4; c++) acc[a][b][c] = 0.f;

    auto load_stage = [&](int ch, int st) {
        uint32_t base = sb + st * PVSTG;
        int k0 = ch << 5;
#pragma unroll
        for (int j = 0; j < 9; j++) {
            int id = tid + j * 256;
            if (id < 256) {
                int t = id >> 7, w = id & 127;
                int row = w >> 2, c16 = w & 3;
                cp16(base + t * PVATSZ + row * PITCHB + c16 * 16,
                     pA[t] + (long)row * 1024 + k0 + c16 * 8);
            } else {
                int idb = id - 256;
                int t = idb >> 10, w = idb & 1023;
                int row = w >> 2, c16 = w & 3;
                cp16(base + 2 * PVATSZ + t * PVBTSZ + row * PITCHB + c16 * 16,
                     pB[t] + (long)(n0 + row) * 1024 + k0 + c16 * 8);
            }
        }
        asm volatile("cp.async.commit_group;" ::: "memory");
    };

    load_stage(0, 0);
    for (int i = 0; i < 32; i++) {
        int st = i & 1;
        if (i + 1 < 32) {
            load_stage(i + 1, st ^ 1);
            asm volatile("cp.async.wait_group 1;" ::: "memory");
        } else {
            asm volatile("cp.async.wait_group 0;" ::: "memory");
        }
        __syncthreads();
        uint32_t sA_h = sb + st * PVSTG, sA_l = sA_h + PVATSZ;
        uint32_t sB_h = sA_h + 2 * PVATSZ, sB_l = sB_h + PVBTSZ;
#pragma unroll
        for (int ks = 0; ks < 2; ks++) {
            uint32_t kb = (uint32_t)(ks * 16 + kadd) * 2;
            uint32_t bh[4][2], bl[4][2];
#pragma unroll
            for (int p = 0; p < 2; p++) {
                uint32_t r[4];
                ldsm4(r, sB_h + (uint32_t)(rowB + p * 16) * PITCHB + kb);
                bh[p*2][0] = r[0]; bh[p*2][1] = r[2];
                bh[p*2+1][0] = r[1]; bh[p*2+1][1] = r[3];
                ldsm4(r, sB_l + (uint32_t)(rowB + p * 16) * PITCHB + kb);
                bl[p*2][0] = r[0]; bl[p*2][1] = r[2];
                bl[p*2+1][0] = r[1]; bl[p*2+1][1] = r[3];
            }
#pragma unroll
            for (int mt = 0; mt < 2; mt++) {
                uint32_t ah[4], al[4];
                ldsm4(ah, sA_h + (uint32_t)(row_off + mt * 16) * PITCHB + kb);
                ldsm4(al, sA_l + (uint32_t)(row_off + mt * 16) * PITCHB + kb);
#pragma unroll
                for (int nt = 0; nt < 4; nt++) {
                    mma16816(acc[mt][nt], ah, bh[nt]);
                    mma16816(acc[mt][nt], ah, bl[nt]);
                    mma16816(acc[mt][nt], al, bh[nt]);
                }
            }
        }
        __syncthreads();
    }

    float* Cb = g_PV + (long)z * 32768;
#pragma unroll
    for (int mt = 0; mt < 2; mt++) {
        int m = mt * 16 + (lane >> 2);
#pragma unroll
        for (int nt = 0; nt < 4; nt++) {
            int n = n0 + wid * 32 + nt * 8 + (lane & 3) * 2;
            *(float2*)(Cb + (long)m * 1024 + n) = *(float2*)&acc[mt][nt][0];
            *(float2*)(Cb + (long)(m + 8) * 1024 + n) = *(float2*)&acc[mt][nt][2];
        }
    }
}

// ---------------- reduce helpers ----------------
__device__ __forceinline__ float wmax(float v) {
#pragma unroll
    for (int o = 16; o; o >>= 1) v = fmaxf(v, __shfl_xor_sync(~0u, v, o));
    return v;
}
__device__ __forceinline__ float wsum(float v) {
#pragma unroll
    for (int o = 16; o; o >>= 1) v += __shfl_xor_sync(~0u, v, o);
    return v;
}

// ---------------- small kernels ----------------
__global__ void k_zero4(float4* p, int n4) {
    int i = blockIdx.x * 256 + threadIdx.x;
    if (i < n4) p[i] = make_float4(0.f, 0.f, 0.f, 0.f);
}
__global__ void k_wrd(const float* __restrict__ W, __nv_bfloat16* __restrict__ h,
                      __nv_bfloat16* __restrict__ l, int CIN) {
    int idx = blockIdx.x * 256 + threadIdx.x;
    int K = CIN * 9;
    int oc = idx / K, rem = idx - oc * K;
    int cc = rem / 9, tap = rem - cc * 9;
    __nv_bfloat16 a, b; bsplit(W[idx], a, b);
    long d = (long)oc * K + tap * CIN + cc;
    h[d] = a; l[d] = b;
}
__global__ void k_pack_w1(const float* __restrict__ Wq, const float* __restrict__ bq,
                          const float* __restrict__ Wk, const float* __restrict__ bk,
                          const float* __restrict__ Wv, const float* __restrict__ bv) {
    int idx = blockIdx.x * 256 + threadIdx.x;
    float v;
    if (idx < 65536) v = Wq[idx];
    else if (idx < 131072) v = Wk[idx - 65536];
    else v = Wv[idx - 131072];
    __nv_bfloat16 a, b; bsplit(v, a, b);
    g_W1h[idx] = a; g_W1l[idx] = b;
    if (idx < 64) g_b1[idx] = bq[idx];
    else if (idx < 128) g_b1[idx] = bk[idx - 64];
    else if (idx < 384) g_b1[idx] = bv[idx - 128];
}
__global__ void k_im2col1(const float* __restrict__ x) {
    __shared__ float t[32][33];
    int k0 = blockIdx.x * 32, n0 = blockIdx.y * 32;
    int tx = threadIdx.x;
#pragma unroll
    for (int it = 0; it < 4; it++) {
        int ty = threadIdx.y + it * 8;
        int k = k0 + ty, n = n0 + tx;
        int c = k >> 2, ky = (k >> 1) & 1, kx = k & 1;
        int b = n >> 10, l = n & 1023, y = l >> 5, xq = l & 31;
        t[ty][tx] = x[(((b * 256 + c) * 64) + (y * 2 + ky)) * 64 + xq * 2 + kx];
    }
    __syncthreads();
#pragma unroll
    for (int it = 0; it < 4; it++) {
        int ty = threadIdx.y + it * 8;
        __nv_bfloat16 a, b; bsplit(t[tx][ty], a, b);
        long o = (long)(n0 + ty) * 1024 + k0 + tx;
        g_X1h[o] = a; g_X1l[o] = b;
    }
}
// pos attention: scores + softmax -> split-bf16 P
__global__ void k_pos_attn() {
    __shared__ float Ks[8][1024];
    int b = blockIdx.z, h = blockIdx.y, tid = threadIdx.x;
    for (int idx = tid; idx < 8192; idx += 256) {
        int d = idx >> 10, k = idx & 1023;
        Ks[d][k] = g_P1[(64 + h * 8 + d) * BL + b * 1024 + k];
    }
    __syncthreads();
    int warp = tid >> 5, lane = tid & 31;
    int qb = blockIdx.x * 64 + warp * 8;
#pragma unroll 1
    for (int qq = 0; qq < 8; qq++) {
        int q = qb + qq;
        float Q[8];
#pragma unroll
        for (int d = 0; d < 8; d++) Q[d] = g_P1[(h * 8 + d) * BL + b * 1024 + q];
        float s[32], mx = -1e30f;
#pragma unroll
        for (int i = 0; i < 32; i++) {
            int k = i * 32 + lane;
            float sc = 0.f;
#pragma unroll
            for (int d = 0; d < 8; d++) sc += Q[d] * Ks[d][k];
            sc *= 0.35355339059327373f;
            s[i] = sc; mx = fmaxf(mx, sc);
        }
        mx = wmax(mx);
        float sum = 0.f;
#pragma unroll
        for (int i = 0; i < 32; i++) { float e = __expf(s[i] - mx); s[i] = e; sum += e; }
        float inv = 1.0f / wsum(sum);
        size_t ob = ((size_t)(b * 8 + h) * 1024 + q) * 1024 + lane;
#pragma unroll
        for (int i = 0; i < 32; i++) {
            __nv_bfloat16 a, c; bsplit(s[i] * inv, a, c);
            g_Pph[ob + i * 32] = a; g_Ppl[ob + i * 32] = c;
        }
    }
}
// V^T split repack: [bh][d][k]
__global__ void k_vtp() {
    int idx = blockIdx.x * 256 + threadIdx.x;   // 2,097,152
    int k = idx & 1023, d = (idx >> 10) & 31, bh = idx >> 15;
    __nv_bfloat16 a, b;
    bsplit(g_P1[(128 + (bh & 7) * 32 + d) * BL + (bh >> 3) * 1024 + k], a, b);
    g_vTph[idx] = a; g_vTpl[idx] = b;
}
// transpose PV [bh][d][q] -> padded ch-last I2; grid(32 qtiles, 64 bh), block(32,8)
__global__ void k_o1t() {
    __shared__ float t[32][33];
    int q0 = blockIdx.x * 32, z = blockIdx.y;
    int b = z >> 3, h = z & 7;
    int tx = threadIdx.x;
#pragma unroll
    for (int it = 0; it < 4; it++) {
        int ty = threadIdx.y + it * 8;   // d
        t[ty][tx] = g_PV[((long)z * 32 + ty) * 1024 + q0 + tx];
    }
    __syncthreads();
#pragma unroll
    for (int it = 0; it < 4; it++) {
        int ty = threadIdx.y + it * 8;   // q
        int q = q0 + ty;
        int y = q >> 5, x = q & 31;
        __nv_bfloat16 a, c; bsplit(t[tx][ty], a, c);
        long o = ((long)(b * 34 + 1 + y) * 34 + 1 + x) * 256 + h * 32 + tx;
        g_I2h[o] = a; g_I2l[o] = c;
    }
}
__global__ void k_cha_proj(const float* __restrict__ x,
                           const float* __restrict__ Wq, const float* __restrict__ bq,
                           const float* __restrict__ Wk, const float* __restrict__ bk,
                           const float* __restrict__ Wv, const float* __restrict__ bv) {
    int l = blockIdx.x * 256 + threadIdx.x;
    int g = blockIdx.y, b = blockIdx.z;
    int i = l >> 5, j = l & 31;
    const float* xp = x + ((b * 256 + g) * 64) * 64;
    float x00 = xp[2*i*64 + 2*j], x01 = xp[2*i*64 + 2*j + 1];
    float x10 = xp[(2*i+1)*64 + 2*j], x11 = xp[(2*i+1)*64 + 2*j + 1];
    int base = (b * 2048 + g * 8) * 1024 + l;
#pragma unroll
    for (int h = 0; h < 8; h++) {
        int w = (g * 8 + h) * 4, o = base + h * 1024;
        float qv = Wq[w]*x00 + Wq[w+1]*x01 + Wq[w+2]*x10 + Wq[w+3]*x11 + bq[g*8+h];
        float kv = Wk[w]*x00 + Wk[w+1]*x01 + Wk[w+2]*x10 + Wk[w+3]*x11 + bk[g*8+h];
        float vv = Wv[w]*x00 + Wv[w+1]*x01 + Wv[w+2]*x10 + Wv[w+3]*x11 + bv[g*8+h];
        __nv_bfloat16 a, c;
        bsplit(qv, a, c); g_qch[o] = a; g_qcl[o] = c;
        bsplit(kv, a, c); g_kch[o] = a; g_kcl[o] = c;
        g_vc[o] = vv;
    }
}
__global__ void k_vcT() {
    __shared__ float t[32][33];
    int z = blockIdx.z, c0 = blockIdx.x * 32, l0 = blockIdx.y * 32;
    int tx = threadIdx.x;
    const float* src = g_vc + (long)z * 262144;
#pragma unroll
    for (int it = 0; it < 4; it++) {
        int ty = threadIdx.y + it * 8;
        t[ty][tx] = src[(c0 + ty) * 1024 + l0 + tx];
    }
    __syncthreads();
#pragma unroll
    for (int it = 0; it < 4; it++) {
        int ty = threadIdx.y + it * 8;
        __nv_bfloat16 a, b; bsplit(t[tx][ty], a, b);
        long o = (long)z * 262144 + (long)(l0 + ty) * 256 + c0 + tx;
        g_vTh[o] = a; g_vTl[o] = b;
    }
}
__global__ void k_cha_softmax() {
    int row = blockIdx.x * 8 + (threadIdx.x >> 5);
    int lane = threadIdx.x & 31;
    const float* r = g_Sc + (long)row * 256;
    float v[8], mx = -1e30f;
#pragma unroll
    for (int j = 0; j < 8; j++) { v[j] = r[j * 32 + lane] * 0.03125f; mx = fmaxf(mx, v[j]); }
    mx = wmax(mx);
    float sum = 0.f;
#pragma unroll
    for (int j = 0; j < 8; j++) { v[j] = __expf(v[j] - mx); sum += v[j]; }
    float inv = 1.0f / wsum(sum);
#pragma unroll
    for (int j = 0; j < 8; j++) {
        __nv_bfloat16 a, b; bsplit(v[j] * inv, a, b);
        long o = (long)row * 256 + j * 32 + lane;
        g_Pch[o] = a; g_Pcl[o] = b;
    }
}
// fused: upsample+residual (pos), convT+residual (cha), channels-last pack -> I3
__global__ void k_fusepack(const float* __restrict__ xp_, const float* __restrict__ xc_,
                           const float* __restrict__ Wt, const float* __restrict__ bt,
                           const float* __restrict__ gp_, const float* __restrict__ gc_) {
    __shared__ float t[32][33];
    int c0 = blockIdx.x * 32, p0 = blockIdx.y * 32, b = blockIdx.z;
    int tx = threadIdx.x;
    float gp = gp_[0], gc = gc_[0];
#pragma unroll
    for (int it = 0; it < 4; it++) {
        int ty = threadIdx.y + it * 8;
        int c = c0 + ty, pix = p0 + tx;
        int Y = pix >> 6, X = pix & 63;
        float v;
        if (c < 256) {
            float sy = Y * 0.5f - 0.25f, sx = X * 0.5f - 0.25f;
            int y0 = (int)floorf(sy); float fy = sy - y0;
            int x0 = (int)floorf(sx); float fx = sx - x0;
            int y1 = min(y0 + 1, 31); y0 = max(y0, 0);
            int x1 = min(x0 + 1, 31); x0 = max(x0, 0);
            const float* p = g_O2 + c * 8192 + b * 1024;
            float u = (1.f - fy) * ((1.f - fx) * p[y0*32+x0] + fx * p[y0*32+x1])
                    + fy * ((1.f - fx) * p[y1*32+x0] + fx * p[y1*32+x1]);
            v = xp_[((b * 256 + c) * 4096) + pix] + gp * u;
        } else {
            int g = c - 256;
            int pp = Y >> 1, ky = Y & 1, qq = X >> 1, kx = X & 1;
            float s = bt[g];
            int ob = (b * 2048 + g * 8) * 1024 + pp * 32 + qq;
#pragma unroll
            for (int i = 0; i < 8; i++)
                s += g_oc[ob + i * 1024] * Wt[(g * 8 + i) * 4 + ky * 2 + kx];
            v = xc_[((b * 256 + g) * 4096) + pix] + gc * s;
        }
        t[ty][tx] = v;
    }
    __syncthreads();
#pragma unroll
    for (int it = 0; it < 4; it++) {
        int ty = threadIdx.y + it * 8;
        int pix = p0 + ty, c = c0 + tx;
        int Y = pix >> 6, X = pix & 63;
        __nv_bfloat16 a, bb; bsplit(t[tx][ty], a, bb);
        long o = ((long)(b * 66 + 1 + Y) * 66 + 1 + X) * 512 + c;
        g_I3h[o] = a; g_I3l[o] = bb;
    }
}

// ---------------- launch ----------------
static void* sym(const void* s) { void* p = nullptr; cudaGetSymbolAddress(&p, s); return p; }

extern "C" void kernel_launch(void* const* d_in, const int* in_sizes, int n_in,
                              void* d_out, int out_size) {
    const float *qkv_pos = (const float*)d_in[0], *qkv_cha = (const float*)d_in[1];
    const float *Wq_pos = (const float*)d_in[2], *bq_pos = (const float*)d_in[3];
    const float *Wk_pos = (const float*)d_in[4], *bk_pos = (const float*)d_in[5];
    const float *Wv_pos = (const float*)d_in[6], *bv_pos = (const float*)d_in[7];
    const float *Wo_pos = (const float*)d_in[8], *bo_pos = (const float*)d_in[9];
    const float *gamma_pos = (const float*)d_in[10];
    const float *Wq_cha = (const float*)d_in[11], *bq_cha = (const float*)d_in[12];
    const float *Wk_cha = (const float*)d_in[13], *bk_cha = (const float*)d_in[14];
    const float *Wv_cha = (const float*)d_in[15], *bv_cha = (const float*)d_in[16];
    const float *Wt_cha = (const float*)d_in[17], *bt_cha = (const float*)d_in[18];
    const float *gamma_cha = (const float*)d_in[19];
    const float *Wf = (const float*)d_in[20], *bf = (const float*)d_in[21];
    float* out = (float*)d_out;

    cudaFuncSetAttribute(tgemm, cudaFuncAttributeMaxDynamicSharedMemorySize, TSMEM);
    cudaFuncSetAttribute(tgemm_conv<5,256,34,false>, cudaFuncAttributeMaxDynamicSharedMemorySize, TSMEM);
    cudaFuncSetAttribute(tgemm_conv<6,512,66,true>, cudaFuncAttributeMaxDynamicSharedMemorySize, TSMEM);
    cudaFuncSetAttribute(tgemm_pv, cudaFuncAttributeMaxDynamicSharedMemorySize, PVSMEM);

    __nv_bfloat16 *pW1h = (__nv_bfloat16*)sym(g_W1h), *pW1l = (__nv_bfloat16*)sym(g_W1l);
    __nv_bfloat16 *pX1h = (__nv_bfloat16*)sym(g_X1h), *pX1l = (__nv_bfloat16*)sym(g_X1l);
    __nv_bfloat16 *pWoh = (__nv_bfloat16*)sym(g_Woh), *pWol = (__nv_bfloat16*)sym(g_Wol);
    __nv_bfloat16 *pI2h = (__nv_bfloat16*)sym(g_I2h), *pI2l = (__nv_bfloat16*)sym(g_I2l);
    __nv_bfloat16 *pWfh = (__nv_bfloat16*)sym(g_Wfh), *pWfl = (__nv_bfloat16*)sym(g_Wfl);
    __nv_bfloat16 *pI3h = (__nv_bfloat16*)sym(g_I3h), *pI3l = (__nv_bfloat16*)sym(g_I3l);
    __nv_bfloat16 *pqch = (__nv_bfloat16*)sym(g_qch), *pqcl = (__nv_bfloat16*)sym(g_qcl);
    __nv_bfloat16 *pkch = (__nv_bfloat16*)sym(g_kch), *pkcl = (__nv_bfloat16*)sym(g_kcl);
    __nv_bfloat16 *pvTh = (__nv_bfloat16*)sym(g_vTh), *pvTl = (__nv_bfloat16*)sym(g_vTl);
    __nv_bfloat16 *pPch = (__nv_bfloat16*)sym(g_Pch), *pPcl = (__nv_bfloat16*)sym(g_Pcl);
    float *pb1 = (float*)sym(g_b1), *pP1 = (float*)sym(g_P1);
    float *pO2 = (float*)sym(g_O2), *pSc = (float*)sym(g_Sc), *poc = (float*)sym(g_oc);

    // ---- POS (tgemm proj placed as launch #4 for ncu slot) ----
    k_pack_w1<<<1536, 256>>>(Wq_pos, bq_pos, Wk_pos, bk_pos, Wv_pos, bv_pos);
    k_im2col1<<<dim3(32, 256), dim3(32, 8)>>>(qkv_pos);
    k_zero4<<<1156, 256>>>((float4*)pI2h, 295936);
    tgemm<<<dim3(64, 3, 1), 256, TSMEM>>>(pW1h, pW1l, pX1h, pX1l, pP1, pb1, 8192, 1024, 0, 0, 0);
    k_zero4<<<1156, 256>>>((float4*)pI2l, 295936);
    k_zero4<<<8712, 256>>>((float4*)pI3h, 2230272);
    k_zero4<<<8712, 256>>>((float4*)pI3l, 2230272);
    k_pos_attn<<<dim3(16, 8, 8), 256>>>();
    k_vtp<<<8192, 256>>>();
    tgemm_pv<<<dim3(4, 1, 64), 256, PVSMEM>>>();
    k_o1t<<<dim3(32, 64), dim3(32, 8)>>>();
    k_wrd<<<2304, 256>>>(Wo_pos, pWoh, pWol, 256);
    tgemm_conv<5,256,34,false><<<dim3(64, 2), 256, TSMEM>>>(pWoh, pWol, pI2h, pI2l, pO2, bo_pos, 8192, 2304);

    // ---- CHA ----
    k_cha_proj<<<dim3(4, 256, 8), 256>>>(qkv_cha, Wq_cha, bq_cha, Wk_cha, bk_cha, Wv_cha, bv_cha);
    k_vcT<<<dim3(8, 32, 64), dim3(32, 8)>>>();
    tgemm<<<dim3(2, 2, 64), 256, TSMEM>>>(pqch, pqcl, pkch, pkcl, pSc, nullptr, 256, 1024, 262144L, 262144L, 65536L);
    k_cha_softmax<<<2048, 256>>>();
    tgemm<<<dim3(8, 2, 64), 256, TSMEM>>>(pPch, pPcl, pvTh, pvTl, poc, nullptr, 1024, 256, 65536L, 262144L, 262144L);

    // ---- fused residual/pack + fusion conv direct to out ----
    k_fusepack<<<dim3(16, 128, 8), dim3(32, 8)>>>(qkv_pos, qkv_cha, Wt_cha, bt_cha, gamma_pos, gamma_cha);
    k_wrd<<<4608, 256>>>(Wf, pWfh, pWfl, 512);
    tgemm_conv<6,512,66,true><<<dim3(256, 2), 256, TSMEM>>>(pWfh, pWfl, pI3h, pI3l, out, bf, 32768, 4608);
}